// round 3
// baseline (speedup 1.0000x reference)
#include <cuda_runtime.h>

#define BB 2
#define NSEQ 2048
#define EE 1024
#define HH 16
#define DD 64
#define MM (BB*NSEQ)   // 4096

// Scratch (allocation-free): Q/K/V in [B,H,N,D] layout, ctx in [B*N, E]
__device__ float g_q[BB*HH*NSEQ*DD];
__device__ float g_k[BB*HH*NSEQ*DD];
__device__ float g_v[BB*HH*NSEQ*DD];
__device__ float g_ctx[MM*EE];

// ---------------------------------------------------------------------------
// Fused QKV GEMM: for z = blockIdx.z in {0,1,2}, computes
//   proj[m][e] = sum_k x[m][k] * W_z[e][k] + b_z[e]
// and scatters into g_q / g_k / g_v in head-split [B,H,N,D] layout.
// BM=BN=128, BK=16, 256 threads, 8x8 micro-tile.
// ---------------------------------------------------------------------------
__global__ __launch_bounds__(256) void qkv_gemm(const float* __restrict__ X,
                                                const float* __restrict__ Wq,
                                                const float* __restrict__ bq,
                                                const float* __restrict__ Wk,
                                                const float* __restrict__ bk,
                                                const float* __restrict__ Wv,
                                                const float* __restrict__ bv)
{
    const int z = blockIdx.z;
    const float* W    = (z == 0) ? Wq : (z == 1) ? Wk : Wv;
    const float* bias = (z == 0) ? bq : (z == 1) ? bk : bv;
    float* dst        = (z == 0) ? g_q : (z == 1) ? g_k : g_v;

    __shared__ float As[16][132];
    __shared__ float Bs[16][132];

    const int tid = threadIdx.x;
    const int tx = tid & 15;
    const int ty = tid >> 4;
    const int m0 = blockIdx.y * 128;
    const int n0 = blockIdx.x * 128;

    float acc[8][8];
#pragma unroll
    for (int i = 0; i < 8; ++i)
#pragma unroll
        for (int j = 0; j < 8; ++j) acc[i][j] = 0.0f;

    const int lr = tid >> 2;        // 0..63
    const int lc = (tid & 3) * 4;   // 0,4,8,12

    for (int kt = 0; kt < EE; kt += 16) {
#pragma unroll
        for (int half = 0; half < 2; ++half) {
            int r = lr + half * 64;
            float4 a = *(const float4*)&X[(size_t)(m0 + r) * EE + kt + lc];
            As[lc + 0][r] = a.x; As[lc + 1][r] = a.y;
            As[lc + 2][r] = a.z; As[lc + 3][r] = a.w;
            float4 b = *(const float4*)&W[(size_t)(n0 + r) * EE + kt + lc];
            Bs[lc + 0][r] = b.x; Bs[lc + 1][r] = b.y;
            Bs[lc + 2][r] = b.z; Bs[lc + 3][r] = b.w;
        }
        __syncthreads();
#pragma unroll
        for (int k = 0; k < 16; ++k) {
            float a[8], b[8];
            *(float4*)&a[0] = *(const float4*)&As[k][ty * 8];
            *(float4*)&a[4] = *(const float4*)&As[k][ty * 8 + 4];
            *(float4*)&b[0] = *(const float4*)&Bs[k][tx * 8];
            *(float4*)&b[4] = *(const float4*)&Bs[k][tx * 8 + 4];
#pragma unroll
            for (int i = 0; i < 8; ++i)
#pragma unroll
                for (int j = 0; j < 8; ++j)
                    acc[i][j] += a[i] * b[j];
        }
        __syncthreads();
    }

    // Epilogue: bias + head-split scatter
#pragma unroll
    for (int i = 0; i < 8; ++i) {
        int m = m0 + ty * 8 + i;
        int b = m >> 11, n = m & (NSEQ - 1);
#pragma unroll
        for (int j = 0; j < 8; ++j) {
            int e = n0 + tx * 8 + j;
            float v = acc[i][j] + bias[e];
            int h = e >> 6, d = e & (DD - 1);
            dst[(((size_t)(b * HH + h)) * NSEQ + n) * DD + d] = v;
        }
    }
}

// ---------------------------------------------------------------------------
// Output projection GEMM: out[m][e] = sum_k g_ctx[m][k] * Wo[e][k] + bo[e]
// ---------------------------------------------------------------------------
__global__ __launch_bounds__(256) void out_gemm(const float* __restrict__ W,
                                                const float* __restrict__ bias,
                                                float* __restrict__ Out)
{
    const float* X = g_ctx;
    __shared__ float As[16][132];
    __shared__ float Bs[16][132];

    const int tid = threadIdx.x;
    const int tx = tid & 15;
    const int ty = tid >> 4;
    const int m0 = blockIdx.y * 128;
    const int n0 = blockIdx.x * 128;

    float acc[8][8];
#pragma unroll
    for (int i = 0; i < 8; ++i)
#pragma unroll
        for (int j = 0; j < 8; ++j) acc[i][j] = 0.0f;

    const int lr = tid >> 2;
    const int lc = (tid & 3) * 4;

    for (int kt = 0; kt < EE; kt += 16) {
#pragma unroll
        for (int half = 0; half < 2; ++half) {
            int r = lr + half * 64;
            float4 a = *(const float4*)&X[(size_t)(m0 + r) * EE + kt + lc];
            As[lc + 0][r] = a.x; As[lc + 1][r] = a.y;
            As[lc + 2][r] = a.z; As[lc + 3][r] = a.w;
            float4 b = *(const float4*)&W[(size_t)(n0 + r) * EE + kt + lc];
            Bs[lc + 0][r] = b.x; Bs[lc + 1][r] = b.y;
            Bs[lc + 2][r] = b.z; Bs[lc + 3][r] = b.w;
        }
        __syncthreads();
#pragma unroll
        for (int k = 0; k < 16; ++k) {
            float a[8], b[8];
            *(float4*)&a[0] = *(const float4*)&As[k][ty * 8];
            *(float4*)&a[4] = *(const float4*)&As[k][ty * 8 + 4];
            *(float4*)&b[0] = *(const float4*)&Bs[k][tx * 8];
            *(float4*)&b[4] = *(const float4*)&Bs[k][tx * 8 + 4];
#pragma unroll
            for (int i = 0; i < 8; ++i)
#pragma unroll
                for (int j = 0; j < 8; ++j)
                    acc[i][j] += a[i] * b[j];
        }
        __syncthreads();
    }

#pragma unroll
    for (int i = 0; i < 8; ++i) {
        int m = m0 + ty * 8 + i;
#pragma unroll
        for (int j = 0; j < 8; ++j) {
            int e = n0 + tx * 8 + j;
            Out[(size_t)m * EE + e] = acc[i][j] + bias[e];
        }
    }
}

// ---------------------------------------------------------------------------
// Flash attention: per (b,h), 64-query tiles streaming 64-key tiles.
// Online softmax (NO logit scaling; output scaled by 1/sqrt(E)=1/32 at the
// end, matching the reference which divides AFTER softmax).
// 256 threads = 16x16, each thread owns a 4x4 of S and a 4x4 of O.
// ---------------------------------------------------------------------------
__global__ __launch_bounds__(256) void flash_attn()
{
    __shared__ float Qs[64 * 64];   // transposed: [d][r]
    __shared__ float KPs[64 * 64];  // K transposed [d][c]; reused for P [r][k]
    __shared__ float Vs[64 * 64];   // natural: [k][d]

    const int tid = threadIdx.x;
    const int tx = tid & 15;
    const int ty = tid >> 4;
    const int bh = blockIdx.y;
    const int q0 = blockIdx.x * 64;

    const float* Qp = g_q + (size_t)bh * NSEQ * DD + (size_t)q0 * DD;
    const float* Kp = g_k + (size_t)bh * NSEQ * DD;
    const float* Vp = g_v + (size_t)bh * NSEQ * DD;

    // Load Q tile transposed into Qs[d][r]
    {
        const int c4 = (tid & 15) * 4;
#pragma unroll
        for (int it = 0; it < 4; ++it) {
            int r = (tid >> 4) + it * 16;
            float4 q = *(const float4*)&Qp[(size_t)r * DD + c4];
            Qs[(c4 + 0) * 64 + r] = q.x;
            Qs[(c4 + 1) * 64 + r] = q.y;
            Qs[(c4 + 2) * 64 + r] = q.z;
            Qs[(c4 + 3) * 64 + r] = q.w;
        }
    }

    float mrun[4], lrun[4], o[4][4];
#pragma unroll
    for (int i = 0; i < 4; ++i) {
        mrun[i] = -1e30f;
        lrun[i] = 0.0f;
#pragma unroll
        for (int j = 0; j < 4; ++j) o[i][j] = 0.0f;
    }

    for (int kt = 0; kt < NSEQ; kt += 64) {
        // Load K (transposed) and V (natural)
        {
            const int c4 = (tid & 15) * 4;
#pragma unroll
            for (int it = 0; it < 4; ++it) {
                int r = (tid >> 4) + it * 16;
                float4 kv = *(const float4*)&Kp[(size_t)(kt + r) * DD + c4];
                KPs[(c4 + 0) * 64 + r] = kv.x;
                KPs[(c4 + 1) * 64 + r] = kv.y;
                KPs[(c4 + 2) * 64 + r] = kv.z;
                KPs[(c4 + 3) * 64 + r] = kv.w;
                float4 vv = *(const float4*)&Vp[(size_t)(kt + r) * DD + c4];
                *(float4*)&Vs[r * 64 + c4] = vv;
            }
        }
        __syncthreads();

        // S = Q K^T  (rows 4ty+i, cols 4tx+j)
        float s[4][4];
#pragma unroll
        for (int i = 0; i < 4; ++i)
#pragma unroll
            for (int j = 0; j < 4; ++j) s[i][j] = 0.0f;

#pragma unroll 8
        for (int d = 0; d < 64; ++d) {
            float4 qv = *(const float4*)&Qs[d * 64 + 4 * ty];
            float4 kv = *(const float4*)&KPs[d * 64 + 4 * tx];
            float qa[4] = {qv.x, qv.y, qv.z, qv.w};
            float ka[4] = {kv.x, kv.y, kv.z, kv.w};
#pragma unroll
            for (int i = 0; i < 4; ++i)
#pragma unroll
                for (int j = 0; j < 4; ++j)
                    s[i][j] += qa[i] * ka[j];
        }
        __syncthreads();  // done reading K tile; KPs will be reused for P

        // Online softmax per row (reduce across 16 tx lanes: lanes stay in
        // their 16-lane half-warp under xor 8,4,2,1)
#pragma unroll
        for (int i = 0; i < 4; ++i) {
            float mt = fmaxf(fmaxf(s[i][0], s[i][1]), fmaxf(s[i][2], s[i][3]));
#pragma unroll
            for (int off = 8; off >= 1; off >>= 1)
                mt = fmaxf(mt, __shfl_xor_sync(0xffffffffu, mt, off));
            float mnew = fmaxf(mrun[i], mt);
            float corr = __expf(mrun[i] - mnew);
            mrun[i] = mnew;
            float ls = 0.0f;
#pragma unroll
            for (int j = 0; j < 4; ++j) {
                s[i][j] = __expf(s[i][j] - mnew);
                ls += s[i][j];
            }
#pragma unroll
            for (int off = 8; off >= 1; off >>= 1)
                ls += __shfl_xor_sync(0xffffffffu, ls, off);
            lrun[i] = lrun[i] * corr + ls;
#pragma unroll
            for (int j = 0; j < 4; ++j) o[i][j] *= corr;
        }

        // Write P into KPs as [r][k] (float4 per row, conflict-free)
#pragma unroll
        for (int i = 0; i < 4; ++i) {
            float4 pv = make_float4(s[i][0], s[i][1], s[i][2], s[i][3]);
            *(float4*)&KPs[(4 * ty + i) * 64 + 4 * tx] = pv;
        }
        __syncthreads();

        // O += P @ V
#pragma unroll 8
        for (int k = 0; k < 64; ++k) {
            float4 vv = *(const float4*)&Vs[k * 64 + 4 * tx];
            float va[4] = {vv.x, vv.y, vv.z, vv.w};
            float pa[4];
#pragma unroll
            for (int i = 0; i < 4; ++i) pa[i] = KPs[(4 * ty + i) * 64 + k];
#pragma unroll
            for (int i = 0; i < 4; ++i)
#pragma unroll
                for (int j = 0; j < 4; ++j)
                    o[i][j] += pa[i] * va[j];
        }
        __syncthreads();
    }

    // Epilogue: normalize, apply the post-softmax 1/sqrt(E) = 1/32 scale,
    // write ctx back in token-major [B*N, E] layout.
    const int b = bh >> 4;
    const int h = bh & (HH - 1);
    const float scale = 1.0f / 32.0f;
#pragma unroll
    for (int i = 0; i < 4; ++i) {
        float inv = scale / lrun[i];
        int n = q0 + 4 * ty + i;
        size_t base = ((size_t)(b * NSEQ + n)) * EE + h * DD + 4 * tx;
        float4 ov = make_float4(o[i][0] * inv, o[i][1] * inv,
                                o[i][2] * inv, o[i][3] * inv);
        *(float4*)&g_ctx[base] = ov;
    }
}

// ---------------------------------------------------------------------------
extern "C" void kernel_launch(void* const* d_in, const int* in_sizes, int n_in,
                              void* d_out, int out_size)
{
    const float* x  = (const float*)d_in[0];
    const float* Wq = (const float*)d_in[1];
    const float* bq = (const float*)d_in[2];
    const float* Wk = (const float*)d_in[3];
    const float* bk = (const float*)d_in[4];
    const float* Wv = (const float*)d_in[5];
    const float* bv = (const float*)d_in[6];
    const float* Wo = (const float*)d_in[7];
    const float* bo = (const float*)d_in[8];
    float* out = (float*)d_out;

    dim3 gqkv(EE / 128, MM / 128, 3);  // (8, 32, 3)
    qkv_gemm<<<gqkv, 256>>>(x, Wq, bq, Wk, bk, Wv, bv);

    flash_attn<<<dim3(NSEQ / 64, BB * HH), 256>>>();

    out_gemm<<<dim3(EE / 128, MM / 128), 256>>>(Wo, bo, out);
}

// round 7
// speedup vs baseline: 1.2943x; 1.2943x over previous
#include <cuda_runtime.h>
#include <cuda_bf16.h>
#include <cstdint>

#define BB 2
#define NSEQ 2048
#define EE 1024
#define HH 16
#define DD 64
#define MM (BB*NSEQ)   // 4096

// ---------------------------------------------------------------------------
// Scratch (allocation-free __device__ globals)
// ---------------------------------------------------------------------------
__device__ float g_q[BB*HH*NSEQ*DD];
__device__ float g_k[BB*HH*NSEQ*DD];
__device__ float g_v[BB*HH*NSEQ*DD];
__device__ float g_ctx[MM*EE];

// bf16 hi/lo splits of x, the four weights, and ctx
__device__ __nv_bfloat16 g_xh[MM*EE];
__device__ __nv_bfloat16 g_xl[MM*EE];
__device__ __nv_bfloat16 g_wh[4*EE*EE];
__device__ __nv_bfloat16 g_wl[4*EE*EE];
__device__ __nv_bfloat16 g_ch[MM*EE];
__device__ __nv_bfloat16 g_cl[MM*EE];

// ---------------------------------------------------------------------------
// Helpers (baseline PTX only: sm_80-era features, valid on sm_103 base target)
// ---------------------------------------------------------------------------
__device__ __forceinline__ uint32_t smem_to_u32(const void* p) {
    uint32_t a;
    asm("{ .reg .u64 t; cvta.to.shared.u64 t, %1; cvt.u32.u64 %0, t; }"
        : "=r"(a) : "l"(p));
    return a;
}

__device__ __forceinline__ void cp_async16(uint32_t dst, const void* src) {
    asm volatile("cp.async.cg.shared.global [%0], [%1], 16;\n"
                 :: "r"(dst), "l"(src));
}

__device__ __forceinline__ void ldsm_x4(uint32_t* r, uint32_t addr) {
    asm volatile("ldmatrix.sync.aligned.m8n8.x4.shared.b16 {%0,%1,%2,%3}, [%4];"
                 : "=r"(r[0]), "=r"(r[1]), "=r"(r[2]), "=r"(r[3]) : "r"(addr));
}

__device__ __forceinline__ void mma16816(float* d, const uint32_t* a,
                                         uint32_t b0, uint32_t b1) {
    asm volatile(
        "mma.sync.aligned.m16n8k16.row.col.f32.bf16.bf16.f32 "
        "{%0,%1,%2,%3}, {%4,%5,%6,%7}, {%8,%9}, {%0,%1,%2,%3};"
        : "+f"(d[0]), "+f"(d[1]), "+f"(d[2]), "+f"(d[3])
        : "r"(a[0]), "r"(a[1]), "r"(a[2]), "r"(a[3]), "r"(b0), "r"(b1));
}

// ---------------------------------------------------------------------------
// Split conversion: fp32 -> bf16 hi + bf16 lo
// ---------------------------------------------------------------------------
__global__ __launch_bounds__(256) void conv_split(const float* __restrict__ x,
                                                  const float* __restrict__ wq,
                                                  const float* __restrict__ wk,
                                                  const float* __restrict__ wv,
                                                  const float* __restrict__ wo)
{
    const int z = blockIdx.z;
    const float* src;
    __nv_bfloat16 *dh, *dl;
    int n;
    if (z == 0) { src = x; dh = g_xh; dl = g_xl; n = MM * EE; }
    else {
        src = (z == 1) ? wq : (z == 2) ? wk : (z == 3) ? wv : wo;
        dh = g_wh + (size_t)(z - 1) * EE * EE;
        dl = g_wl + (size_t)(z - 1) * EE * EE;
        n = EE * EE;
    }
    int stride = gridDim.x * blockDim.x;
    for (int i = blockIdx.x * blockDim.x + threadIdx.x; i < n; i += stride) {
        float v = src[i];
        __nv_bfloat16 h = __float2bfloat16(v);
        dh[i] = h;
        dl[i] = __float2bfloat16(v - __bfloat162float(h));
    }
}

__global__ __launch_bounds__(256) void conv_ctx()
{
    int stride = gridDim.x * blockDim.x;
    for (int i = blockIdx.x * blockDim.x + threadIdx.x; i < MM * EE; i += stride) {
        float v = g_ctx[i];
        __nv_bfloat16 h = __float2bfloat16(v);
        g_ch[i] = h;
        g_cl[i] = __float2bfloat16(v - __bfloat162float(h));
    }
}

// ---------------------------------------------------------------------------
// mma.sync bf16 GEMM with hi/lo split: C = A@B^T over K'=3*1024.
// Segments: (Ah,Bh), (Al,Bh), (Ah,Bl) accumulate into the same fp32 regs.
// BM=BN=128, BK=32, 256 threads = 8 warps (2 M x 4 N), warp tile 64x32.
// Smem rows padded to 40 bf16 (80 B) -> ldmatrix conflict-free.
// 4-buffer cp.async pipeline.
// mode 0: A=x-splits, B=W[blockIdx.z], scatter to g_q/g_k/g_v head-split.
// mode 1: A=ctx-splits, B=Wo, write [M,E] to outp.
// ---------------------------------------------------------------------------
#define BKT 32
#define SEGK (EE / BKT)      // 32
#define TOTK (3 * SEGK)      // 96
#define ROWPAD 40            // bf16 elems per smem row (80 B)
#define TILEB (128 * ROWPAD * 2)   // 10240 B per operand tile
#define STAGE_B (2 * TILEB)        // 20480 B per stage (A + B)
#define GNBUF 4
#define GSMEM (GNBUF * STAGE_B)    // 81920 B

__device__ __forceinline__ void g_load_stage(uint32_t sb, int s, int tid,
                                             int m0, int n0,
                                             const __nv_bfloat16* Ah,
                                             const __nv_bfloat16* Al,
                                             const __nv_bfloat16* Bh,
                                             const __nv_bfloat16* Bl)
{
    const int seg = s / SEGK;
    const int k0  = (s % SEGK) * BKT;
    const __nv_bfloat16* A = (seg == 1) ? Al : Ah;
    const __nv_bfloat16* B = (seg == 2) ? Bl : Bh;
    const uint32_t abase = sb + (uint32_t)(s % GNBUF) * STAGE_B;
    const uint32_t bbase = abase + TILEB;
#pragma unroll
    for (int i = 0; i < 2; ++i) {
        int c = tid + i * 256;       // 0..511
        int row = c >> 2;            // 0..127
        int cg  = c & 3;             // 16B chunk within 64B row
        uint32_t dst = (uint32_t)(row * 80 + cg * 16);
        cp_async16(abase + dst, A + (size_t)(m0 + row) * EE + k0 + cg * 8);
        cp_async16(bbase + dst, B + (size_t)(n0 + row) * EE + k0 + cg * 8);
    }
    asm volatile("cp.async.commit_group;\n" ::: "memory");
}

__global__ __launch_bounds__(256, 1) void mma_gemm(int mode,
                                                   const float* __restrict__ bq,
                                                   const float* __restrict__ bk,
                                                   const float* __restrict__ bv,
                                                   const float* __restrict__ bo,
                                                   float* __restrict__ outp)
{
    extern __shared__ __align__(16) unsigned char sm_raw[];
    const uint32_t sb = smem_to_u32(sm_raw);

    const int tid = threadIdx.x;
    const int wid = tid >> 5;
    const int lane = tid & 31;
    const int wm = wid >> 2;            // 0..1 (M)
    const int wn = wid & 3;             // 0..3 (N)
    const int m0 = blockIdx.y * 128;
    const int n0 = blockIdx.x * 128;
    const int widx = (mode == 0) ? (int)blockIdx.z : 3;

    const __nv_bfloat16* Ah = (mode == 0) ? g_xh : g_ch;
    const __nv_bfloat16* Al = (mode == 0) ? g_xl : g_cl;
    const __nv_bfloat16* Bh = g_wh + (size_t)widx * EE * EE;
    const __nv_bfloat16* Bl = g_wl + (size_t)widx * EE * EE;

    float acc[4][4][4];
#pragma unroll
    for (int mi = 0; mi < 4; ++mi)
#pragma unroll
        for (int nj = 0; nj < 4; ++nj)
#pragma unroll
            for (int r = 0; r < 4; ++r) acc[mi][nj][r] = 0.0f;

    // Prologue: 3 stages in flight
    g_load_stage(sb, 0, tid, m0, n0, Ah, Al, Bh, Bl);
    g_load_stage(sb, 1, tid, m0, n0, Ah, Al, Bh, Bl);
    g_load_stage(sb, 2, tid, m0, n0, Ah, Al, Bh, Bl);

    for (int s = 0; s < TOTK; ++s) {
        if (s < TOTK - 2)
            asm volatile("cp.async.wait_group 2;\n" ::: "memory");
        else if (s == TOTK - 2)
            asm volatile("cp.async.wait_group 1;\n" ::: "memory");
        else
            asm volatile("cp.async.wait_group 0;\n" ::: "memory");
        __syncthreads();

        const uint32_t abuf = sb + (uint32_t)(s % GNBUF) * STAGE_B;
        const uint32_t bbuf = abuf + TILEB;

#pragma unroll
        for (int ks = 0; ks < 2; ++ks) {
            uint32_t af[4][4];
#pragma unroll
            for (int mi = 0; mi < 4; ++mi) {
                int r = wm * 64 + mi * 16 + (lane & 15);
                uint32_t addr = abuf + (uint32_t)(r * 80 + ks * 32 + (lane >> 4) * 16);
                ldsm_x4(af[mi], addr);
            }
            uint32_t bfr[2][4];
#pragma unroll
            for (int np = 0; np < 2; ++np) {
                int g = lane >> 3;   // 0..3: (nsub, khalf) = (g>>1, g&1)
                int r = wn * 32 + np * 16 + (g >> 1) * 8 + (lane & 7);
                uint32_t addr = bbuf + (uint32_t)(r * 80 + ks * 32 + (g & 1) * 16);
                ldsm_x4(bfr[np], addr);
            }
#pragma unroll
            for (int mi = 0; mi < 4; ++mi)
#pragma unroll
                for (int nj = 0; nj < 4; ++nj)
                    mma16816(acc[mi][nj], af[mi],
                             bfr[nj >> 1][(nj & 1) * 2],
                             bfr[nj >> 1][(nj & 1) * 2 + 1]);
        }

        if (s + 3 < TOTK)
            g_load_stage(sb, s + 3, tid, m0, n0, Ah, Al, Bh, Bl);
    }

    // Epilogue: d0,d1 -> (row, c0..c0+1); d2,d3 -> (row+8, c0..c0+1)
    const int r_base = m0 + wm * 64 + (lane >> 2);
    const int c_lane = (lane & 3) * 2;

    if (mode == 1) {
#pragma unroll
        for (int mi = 0; mi < 4; ++mi) {
#pragma unroll
            for (int nj = 0; nj < 4; ++nj) {
                int e = n0 + wn * 32 + nj * 8 + c_lane;
                int r = r_base + mi * 16;
                float2 v0 = make_float2(acc[mi][nj][0] + bo[e],
                                        acc[mi][nj][1] + bo[e + 1]);
                *(float2*)&outp[(size_t)r * EE + e] = v0;
                float2 v1 = make_float2(acc[mi][nj][2] + bo[e],
                                        acc[mi][nj][3] + bo[e + 1]);
                *(float2*)&outp[(size_t)(r + 8) * EE + e] = v1;
            }
        }
    } else {
        const float* bias = (widx == 0) ? bq : (widx == 1) ? bk : bv;
        float* dst = (widx == 0) ? g_q : (widx == 1) ? g_k : g_v;
#pragma unroll
        for (int mi = 0; mi < 4; ++mi) {
#pragma unroll
            for (int nj = 0; nj < 4; ++nj) {
                int e = n0 + wn * 32 + nj * 8 + c_lane;
                int h = e >> 6, d = e & (DD - 1);
#pragma unroll
                for (int half = 0; half < 2; ++half) {
                    int m = r_base + mi * 16 + half * 8;
                    int b = m >> 11, n = m & (NSEQ - 1);
                    float2 v = make_float2(acc[mi][nj][half * 2 + 0] + bias[e],
                                           acc[mi][nj][half * 2 + 1] + bias[e + 1]);
                    *(float2*)&dst[(((size_t)(b * HH + h)) * NSEQ + n) * DD + d] = v;
                }
            }
        }
    }
}

// ---------------------------------------------------------------------------
// Flash attention (UNCHANGED from passing R3 kernel)
// ---------------------------------------------------------------------------
__global__ __launch_bounds__(256) void flash_attn()
{
    __shared__ float Qs[64 * 64];   // transposed: [d][r]
    __shared__ float KPs[64 * 64];  // K transposed [d][c]; reused for P [r][k]
    __shared__ float Vs[64 * 64];   // natural: [k][d]

    const int tid = threadIdx.x;
    const int tx = tid & 15;
    const int ty = tid >> 4;
    const int bh = blockIdx.y;
    const int q0 = blockIdx.x * 64;

    const float* Qp = g_q + (size_t)bh * NSEQ * DD + (size_t)q0 * DD;
    const float* Kp = g_k + (size_t)bh * NSEQ * DD;
    const float* Vp = g_v + (size_t)bh * NSEQ * DD;

    {
        const int c4 = (tid & 15) * 4;
#pragma unroll
        for (int it = 0; it < 4; ++it) {
            int r = (tid >> 4) + it * 16;
            float4 q = *(const float4*)&Qp[(size_t)r * DD + c4];
            Qs[(c4 + 0) * 64 + r] = q.x;
            Qs[(c4 + 1) * 64 + r] = q.y;
            Qs[(c4 + 2) * 64 + r] = q.z;
            Qs[(c4 + 3) * 64 + r] = q.w;
        }
    }

    float mrun[4], lrun[4], o[4][4];
#pragma unroll
    for (int i = 0; i < 4; ++i) {
        mrun[i] = -1e30f;
        lrun[i] = 0.0f;
#pragma unroll
        for (int j = 0; j < 4; ++j) o[i][j] = 0.0f;
    }

    for (int kt = 0; kt < NSEQ; kt += 64) {
        {
            const int c4 = (tid & 15) * 4;
#pragma unroll
            for (int it = 0; it < 4; ++it) {
                int r = (tid >> 4) + it * 16;
                float4 kv = *(const float4*)&Kp[(size_t)(kt + r) * DD + c4];
                KPs[(c4 + 0) * 64 + r] = kv.x;
                KPs[(c4 + 1) * 64 + r] = kv.y;
                KPs[(c4 + 2) * 64 + r] = kv.z;
                KPs[(c4 + 3) * 64 + r] = kv.w;
                float4 vv = *(const float4*)&Vp[(size_t)(kt + r) * DD + c4];
                *(float4*)&Vs[r * 64 + c4] = vv;
            }
        }
        __syncthreads();

        float s[4][4];
#pragma unroll
        for (int i = 0; i < 4; ++i)
#pragma unroll
            for (int j = 0; j < 4; ++j) s[i][j] = 0.0f;

#pragma unroll 8
        for (int d = 0; d < 64; ++d) {
            float4 qv = *(const float4*)&Qs[d * 64 + 4 * ty];
            float4 kv = *(const float4*)&KPs[d * 64 + 4 * tx];
            float qa[4] = {qv.x, qv.y, qv.z, qv.w};
            float ka[4] = {kv.x, kv.y, kv.z, kv.w};
#pragma unroll
            for (int i = 0; i < 4; ++i)
#pragma unroll
                for (int j = 0; j < 4; ++j)
                    s[i][j] += qa[i] * ka[j];
        }
        __syncthreads();

#pragma unroll
        for (int i = 0; i < 4; ++i) {
            float mt = fmaxf(fmaxf(s[i][0], s[i][1]), fmaxf(s[i][2], s[i][3]));
#pragma unroll
            for (int off = 8; off >= 1; off >>= 1)
                mt = fmaxf(mt, __shfl_xor_sync(0xffffffffu, mt, off));
            float mnew = fmaxf(mrun[i], mt);
            float corr = __expf(mrun[i] - mnew);
            mrun[i] = mnew;
            float ls = 0.0f;
#pragma unroll
            for (int j = 0; j < 4; ++j) {
                s[i][j] = __expf(s[i][j] - mnew);
                ls += s[i][j];
            }
#pragma unroll
            for (int off = 8; off >= 1; off >>= 1)
                ls += __shfl_xor_sync(0xffffffffu, ls, off);
            lrun[i] = lrun[i] * corr + ls;
#pragma unroll
            for (int j = 0; j < 4; ++j) o[i][j] *= corr;
        }

#pragma unroll
        for (int i = 0; i < 4; ++i) {
            float4 pv = make_float4(s[i][0], s[i][1], s[i][2], s[i][3]);
            *(float4*)&KPs[(4 * ty + i) * 64 + 4 * tx] = pv;
        }
        __syncthreads();

#pragma unroll 8
        for (int k = 0; k < 64; ++k) {
            float4 vv = *(const float4*)&Vs[k * 64 + 4 * tx];
            float va[4] = {vv.x, vv.y, vv.z, vv.w};
            float pa[4];
#pragma unroll
            for (int i = 0; i < 4; ++i) pa[i] = KPs[(4 * ty + i) * 64 + k];
#pragma unroll
            for (int i = 0; i < 4; ++i)
#pragma unroll
                for (int j = 0; j < 4; ++j)
                    o[i][j] += pa[i] * va[j];
        }
        __syncthreads();
    }

    const int b = bh >> 4;
    const int h = bh & (HH - 1);
    const float scale = 1.0f / 32.0f;
#pragma unroll
    for (int i = 0; i < 4; ++i) {
        float inv = scale / lrun[i];
        int n = q0 + 4 * ty + i;
        size_t base = ((size_t)(b * NSEQ + n)) * EE + h * DD + 4 * tx;
        float4 ov = make_float4(o[i][0] * inv, o[i][1] * inv,
                                o[i][2] * inv, o[i][3] * inv);
        *(float4*)&g_ctx[base] = ov;
    }
}

// ---------------------------------------------------------------------------
extern "C" void kernel_launch(void* const* d_in, const int* in_sizes, int n_in,
                              void* d_out, int out_size)
{
    const float* x  = (const float*)d_in[0];
    const float* Wq = (const float*)d_in[1];
    const float* bq = (const float*)d_in[2];
    const float* Wk = (const float*)d_in[3];
    const float* bk = (const float*)d_in[4];
    const float* Wv = (const float*)d_in[5];
    const float* bv = (const float*)d_in[6];
    const float* Wo = (const float*)d_in[7];
    const float* bo = (const float*)d_in[8];
    float* out = (float*)d_out;

    cudaFuncSetAttribute(mma_gemm, cudaFuncAttributeMaxDynamicSharedMemorySize,
                         GSMEM);

    conv_split<<<dim3(1024, 1, 5), 256>>>(x, Wq, Wk, Wv, Wo);

    mma_gemm<<<dim3(EE / 128, MM / 128, 3), 256, GSMEM>>>(
        0, bq, bk, bv, bo, nullptr);

    flash_attn<<<dim3(NSEQ / 64, BB * HH), 256>>>();

    conv_ctx<<<2048, 256>>>();

    mma_gemm<<<dim3(EE / 128, MM / 128, 1), 256, GSMEM>>>(
        1, bq, bk, bv, bo, out);
}

// round 8
// speedup vs baseline: 3.0509x; 2.3572x over previous
#include <cuda_runtime.h>
#include <cuda_bf16.h>
#include <cuda_fp16.h>
#include <cstdint>

#define BB 2
#define NSEQ 2048
#define EE 1024
#define HH 16
#define DD 64
#define MM (BB*NSEQ)   // 4096
#define LOG2E_F 1.4426950408889634f

// ---------------------------------------------------------------------------
// Scratch (allocation-free __device__ globals)
// ---------------------------------------------------------------------------
__device__ float g_ctx[MM*EE];

// fp16 attention operands, [B,H,N,D]; Q pre-scaled by log2(e), hi/lo split
__device__ __half g_q16h[BB*HH*NSEQ*DD];
__device__ __half g_q16l[BB*HH*NSEQ*DD];
__device__ __half g_k16[BB*HH*NSEQ*DD];
__device__ __half g_v16[BB*HH*NSEQ*DD];

// bf16 hi/lo splits of x, the four weights, and ctx (for projections)
__device__ __nv_bfloat16 g_xh[MM*EE];
__device__ __nv_bfloat16 g_xl[MM*EE];
__device__ __nv_bfloat16 g_wh[4*EE*EE];
__device__ __nv_bfloat16 g_wl[4*EE*EE];
__device__ __nv_bfloat16 g_ch[MM*EE];
__device__ __nv_bfloat16 g_cl[MM*EE];

// ---------------------------------------------------------------------------
// Helpers (baseline PTX only — sm_80-era features, valid on compute_103 base)
// ---------------------------------------------------------------------------
__device__ __forceinline__ uint32_t smem_to_u32(const void* p) {
    uint32_t a;
    asm("{ .reg .u64 t; cvta.to.shared.u64 t, %1; cvt.u32.u64 %0, t; }"
        : "=r"(a) : "l"(p));
    return a;
}

__device__ __forceinline__ void cp_async16(uint32_t dst, const void* src) {
    asm volatile("cp.async.cg.shared.global [%0], [%1], 16;\n"
                 :: "r"(dst), "l"(src));
}

__device__ __forceinline__ void ldsm_x4(uint32_t* r, uint32_t addr) {
    asm volatile("ldmatrix.sync.aligned.m8n8.x4.shared.b16 {%0,%1,%2,%3}, [%4];"
                 : "=r"(r[0]), "=r"(r[1]), "=r"(r[2]), "=r"(r[3]) : "r"(addr));
}

__device__ __forceinline__ void ldsm_x4_t(uint32_t* r, uint32_t addr) {
    asm volatile("ldmatrix.sync.aligned.m8n8.x4.trans.shared.b16 {%0,%1,%2,%3}, [%4];"
                 : "=r"(r[0]), "=r"(r[1]), "=r"(r[2]), "=r"(r[3]) : "r"(addr));
}

__device__ __forceinline__ void mma16816_bf(float* d, const uint32_t* a,
                                            uint32_t b0, uint32_t b1) {
    asm volatile(
        "mma.sync.aligned.m16n8k16.row.col.f32.bf16.bf16.f32 "
        "{%0,%1,%2,%3}, {%4,%5,%6,%7}, {%8,%9}, {%0,%1,%2,%3};"
        : "+f"(d[0]), "+f"(d[1]), "+f"(d[2]), "+f"(d[3])
        : "r"(a[0]), "r"(a[1]), "r"(a[2]), "r"(a[3]), "r"(b0), "r"(b1));
}

__device__ __forceinline__ void mma16816_f16(float* d, const uint32_t* a,
                                             uint32_t b0, uint32_t b1) {
    asm volatile(
        "mma.sync.aligned.m16n8k16.row.col.f32.f16.f16.f32 "
        "{%0,%1,%2,%3}, {%4,%5,%6,%7}, {%8,%9}, {%0,%1,%2,%3};"
        : "+f"(d[0]), "+f"(d[1]), "+f"(d[2]), "+f"(d[3])
        : "r"(a[0]), "r"(a[1]), "r"(a[2]), "r"(a[3]), "r"(b0), "r"(b1));
}

// exp2 via FFMA pipe (no MUFU): round-trick + degree-5 Taylor, arg clamped
__device__ __forceinline__ float exp2p(float f) {
    f = fmaxf(f, -30.0f);
    float y = f + 12582912.0f;                       // 1.5*2^23
    int n = __float_as_int(y) - 0x4B400000;
    float fr = f - (y - 12582912.0f);                // [-0.5, 0.5]
    float r = 0.0013333558f;
    r = r * fr + 0.0096181291f;
    r = r * fr + 0.0555041087f;
    r = r * fr + 0.2402265070f;
    r = r * fr + 0.6931471806f;
    r = r * fr + 1.0f;
    return r * __int_as_float(0x3F800000 + (n << 23));
}

// ---------------------------------------------------------------------------
// Split conversion: fp32 -> bf16 hi + bf16 lo
// ---------------------------------------------------------------------------
__global__ __launch_bounds__(256) void conv_split(const float* __restrict__ x,
                                                  const float* __restrict__ wq,
                                                  const float* __restrict__ wk,
                                                  const float* __restrict__ wv,
                                                  const float* __restrict__ wo)
{
    const int z = blockIdx.z;
    const float* src;
    __nv_bfloat16 *dh, *dl;
    int n;
    if (z == 0) { src = x; dh = g_xh; dl = g_xl; n = MM * EE; }
    else {
        src = (z == 1) ? wq : (z == 2) ? wk : (z == 3) ? wv : wo;
        dh = g_wh + (size_t)(z - 1) * EE * EE;
        dl = g_wl + (size_t)(z - 1) * EE * EE;
        n = EE * EE;
    }
    int stride = gridDim.x * blockDim.x;
    for (int i = blockIdx.x * blockDim.x + threadIdx.x; i < n; i += stride) {
        float v = src[i];
        __nv_bfloat16 h = __float2bfloat16(v);
        dh[i] = h;
        dl[i] = __float2bfloat16(v - __bfloat162float(h));
    }
}

__global__ __launch_bounds__(256) void conv_ctx()
{
    int stride = gridDim.x * blockDim.x;
    for (int i = blockIdx.x * blockDim.x + threadIdx.x; i < MM * EE; i += stride) {
        float v = g_ctx[i];
        __nv_bfloat16 h = __float2bfloat16(v);
        g_ch[i] = h;
        g_cl[i] = __float2bfloat16(v - __bfloat162float(h));
    }
}

// ---------------------------------------------------------------------------
// mma.sync bf16 projection GEMM with hi/lo split (validated in R7).
// mode 0: epilogue writes fp16 Q(hi/lo, *log2e)/K/V head-split.
// mode 1: A=ctx-splits, B=Wo, write fp32 [M,E] to outp.
// ---------------------------------------------------------------------------
#define BKT 32
#define SEGK (EE / BKT)      // 32
#define TOTK (3 * SEGK)      // 96
#define TILEB (128 * 40 * 2)       // 10240 B per operand tile (80B rows)
#define STAGE_B (2 * TILEB)        // 20480 B
#define GNBUF 4
#define GSMEM (GNBUF * STAGE_B)    // 81920 B

__device__ __forceinline__ void g_load_stage(uint32_t sb, int s, int tid,
                                             int m0, int n0,
                                             const __nv_bfloat16* Ah,
                                             const __nv_bfloat16* Al,
                                             const __nv_bfloat16* Bh,
                                             const __nv_bfloat16* Bl)
{
    const int seg = s / SEGK;
    const int k0  = (s % SEGK) * BKT;
    const __nv_bfloat16* A = (seg == 1) ? Al : Ah;
    const __nv_bfloat16* B = (seg == 2) ? Bl : Bh;
    const uint32_t abase = sb + (uint32_t)(s % GNBUF) * STAGE_B;
    const uint32_t bbase = abase + TILEB;
#pragma unroll
    for (int i = 0; i < 2; ++i) {
        int c = tid + i * 256;
        int row = c >> 2;
        int cg  = c & 3;
        uint32_t dst = (uint32_t)(row * 80 + cg * 16);
        cp_async16(abase + dst, A + (size_t)(m0 + row) * EE + k0 + cg * 8);
        cp_async16(bbase + dst, B + (size_t)(n0 + row) * EE + k0 + cg * 8);
    }
    asm volatile("cp.async.commit_group;\n" ::: "memory");
}

__global__ __launch_bounds__(256, 1) void mma_gemm(int mode,
                                                   const float* __restrict__ bq,
                                                   const float* __restrict__ bk,
                                                   const float* __restrict__ bv,
                                                   const float* __restrict__ bo,
                                                   float* __restrict__ outp)
{
    extern __shared__ __align__(16) unsigned char sm_raw[];
    const uint32_t sb = smem_to_u32(sm_raw);

    const int tid = threadIdx.x;
    const int wid = tid >> 5;
    const int lane = tid & 31;
    const int wm = wid >> 2;
    const int wn = wid & 3;
    const int m0 = blockIdx.y * 128;
    const int n0 = blockIdx.x * 128;
    const int widx = (mode == 0) ? (int)blockIdx.z : 3;

    const __nv_bfloat16* Ah = (mode == 0) ? g_xh : g_ch;
    const __nv_bfloat16* Al = (mode == 0) ? g_xl : g_cl;
    const __nv_bfloat16* Bh = g_wh + (size_t)widx * EE * EE;
    const __nv_bfloat16* Bl = g_wl + (size_t)widx * EE * EE;

    float acc[4][4][4];
#pragma unroll
    for (int mi = 0; mi < 4; ++mi)
#pragma unroll
        for (int nj = 0; nj < 4; ++nj)
#pragma unroll
            for (int r = 0; r < 4; ++r) acc[mi][nj][r] = 0.0f;

    g_load_stage(sb, 0, tid, m0, n0, Ah, Al, Bh, Bl);
    g_load_stage(sb, 1, tid, m0, n0, Ah, Al, Bh, Bl);
    g_load_stage(sb, 2, tid, m0, n0, Ah, Al, Bh, Bl);

    for (int s = 0; s < TOTK; ++s) {
        if (s < TOTK - 2)
            asm volatile("cp.async.wait_group 2;\n" ::: "memory");
        else if (s == TOTK - 2)
            asm volatile("cp.async.wait_group 1;\n" ::: "memory");
        else
            asm volatile("cp.async.wait_group 0;\n" ::: "memory");
        __syncthreads();

        const uint32_t abuf = sb + (uint32_t)(s % GNBUF) * STAGE_B;
        const uint32_t bbuf = abuf + TILEB;

#pragma unroll
        for (int ks = 0; ks < 2; ++ks) {
            uint32_t af[4][4];
#pragma unroll
            for (int mi = 0; mi < 4; ++mi) {
                int r = wm * 64 + mi * 16 + (lane & 15);
                uint32_t addr = abuf + (uint32_t)(r * 80 + ks * 32 + (lane >> 4) * 16);
                ldsm_x4(af[mi], addr);
            }
            uint32_t bfr[2][4];
#pragma unroll
            for (int np = 0; np < 2; ++np) {
                int g = lane >> 3;
                int r = wn * 32 + np * 16 + (g >> 1) * 8 + (lane & 7);
                uint32_t addr = bbuf + (uint32_t)(r * 80 + ks * 32 + (g & 1) * 16);
                ldsm_x4(bfr[np], addr);
            }
#pragma unroll
            for (int mi = 0; mi < 4; ++mi)
#pragma unroll
                for (int nj = 0; nj < 4; ++nj)
                    mma16816_bf(acc[mi][nj], af[mi],
                                bfr[nj >> 1][(nj & 1) * 2],
                                bfr[nj >> 1][(nj & 1) * 2 + 1]);
        }

        if (s + 3 < TOTK)
            g_load_stage(sb, s + 3, tid, m0, n0, Ah, Al, Bh, Bl);
    }

    const int r_base = m0 + wm * 64 + (lane >> 2);
    const int c_lane = (lane & 3) * 2;

    if (mode == 1) {
#pragma unroll
        for (int mi = 0; mi < 4; ++mi) {
#pragma unroll
            for (int nj = 0; nj < 4; ++nj) {
                int e = n0 + wn * 32 + nj * 8 + c_lane;
                int r = r_base + mi * 16;
                float2 v0 = make_float2(acc[mi][nj][0] + bo[e],
                                        acc[mi][nj][1] + bo[e + 1]);
                *(float2*)&outp[(size_t)r * EE + e] = v0;
                float2 v1 = make_float2(acc[mi][nj][2] + bo[e],
                                        acc[mi][nj][3] + bo[e + 1]);
                *(float2*)&outp[(size_t)(r + 8) * EE + e] = v1;
            }
        }
    } else {
        const float* bias = (widx == 0) ? bq : (widx == 1) ? bk : bv;
#pragma unroll
        for (int mi = 0; mi < 4; ++mi) {
#pragma unroll
            for (int nj = 0; nj < 4; ++nj) {
                int e = n0 + wn * 32 + nj * 8 + c_lane;
                int h = e >> 6, d = e & (DD - 1);
#pragma unroll
                for (int half = 0; half < 2; ++half) {
                    int m = r_base + mi * 16 + half * 8;
                    int b = m >> 11, n = m & (NSEQ - 1);
                    float v0 = acc[mi][nj][half * 2 + 0] + bias[e];
                    float v1 = acc[mi][nj][half * 2 + 1] + bias[e + 1];
                    size_t idx = (((size_t)(b * HH + h)) * NSEQ + n) * DD + d;
                    if (widx == 0) {
                        float s0 = v0 * LOG2E_F, s1 = v1 * LOG2E_F;
                        __half h0 = __float2half_rn(s0);
                        __half h1 = __float2half_rn(s1);
                        *(__half2*)&g_q16h[idx] = __halves2half2(h0, h1);
                        __half l0 = __float2half_rn(s0 - __half2float(h0));
                        __half l1 = __float2half_rn(s1 - __half2float(h1));
                        *(__half2*)&g_q16l[idx] = __halves2half2(l0, l1);
                    } else if (widx == 1) {
                        *(__half2*)&g_k16[idx] = __floats2half2_rn(v0, v1);
                    } else {
                        *(__half2*)&g_v16[idx] = __floats2half2_rn(v0, v1);
                    }
                }
            }
        }
    }
}

// ---------------------------------------------------------------------------
// HMMA flash attention. Per (b,h): 128 q-rows/CTA, 8 warps x 16 rows.
// S = (Qh + Ql) @ K^T (2 fp16 passes, logits pre-scaled by log2e).
// Online softmax with exp2 polynomial (FFMA pipe, no MUFU).
// O += P @ V, P/V plain fp16 (P converts accum->A-frag in registers).
// KV: 3-buffer cp.async pipeline, 144B row stride (conflict-free ldmatrix).
// ---------------------------------------------------------------------------
#define FROW 144                  // bytes per smem row (64 fp16 + pad)
#define KVTILE_B (64 * FROW)      // 9216
#define FBUF_B (2 * KVTILE_B)     // K + V per stage: 18432
#define FSMEM (3 * FBUF_B)        // 55296

__device__ __forceinline__ void f_load_kv(uint32_t sb, int buf, int kt, int tid,
                                          const __half* Kp, const __half* Vp)
{
    const uint32_t kb = sb + (uint32_t)buf * FBUF_B;
#pragma unroll
    for (int i = 0; i < 2; ++i) {
        int c = tid + i * 256;       // 0..511
        int row = c >> 3;            // 0..63
        int cg = c & 7;
        uint32_t dst = (uint32_t)(row * FROW + cg * 16);
        cp_async16(kb + dst, Kp + (size_t)(kt * 64 + row) * DD + cg * 8);
        cp_async16(kb + KVTILE_B + dst, Vp + (size_t)(kt * 64 + row) * DD + cg * 8);
    }
    asm volatile("cp.async.commit_group;\n" ::: "memory");
}

__global__ __launch_bounds__(256, 1) void flash_mma()
{
    extern __shared__ __align__(16) unsigned char fsm[];
    const uint32_t sb = smem_to_u32(fsm);

    const int tid = threadIdx.x;
    const int wid = tid >> 5;
    const int lane = tid & 31;
    const int bh = blockIdx.y;
    const int q0 = blockIdx.x * 128;

    const __half* Qh = g_q16h + (size_t)bh * NSEQ * DD + (size_t)q0 * DD;
    const __half* Ql = g_q16l + (size_t)bh * NSEQ * DD + (size_t)q0 * DD;
    const __half* Kp = g_k16 + (size_t)bh * NSEQ * DD;
    const __half* Vp = g_v16 + (size_t)bh * NSEQ * DD;

    // ---- Stage Q (hi at sb, lo at sb+128*FROW) and load fragments ----
#pragma unroll
    for (int i = 0; i < 4; ++i) {
        int c = tid + i * 256;       // 0..1023
        int row = c >> 3;            // 0..127
        int cg = c & 7;
        uint32_t dst = (uint32_t)(row * FROW + cg * 16);
        cp_async16(sb + dst, Qh + (size_t)row * DD + cg * 8);
        cp_async16(sb + 128 * FROW + dst, Ql + (size_t)row * DD + cg * 8);
    }
    asm volatile("cp.async.commit_group;\n" ::: "memory");
    asm volatile("cp.async.wait_group 0;\n" ::: "memory");
    __syncthreads();

    uint32_t qhf[4][4], qlf[4][4];
#pragma unroll
    for (int ks = 0; ks < 4; ++ks) {
        uint32_t addr = sb + (uint32_t)((wid * 16 + (lane & 15)) * FROW
                                        + ks * 32 + (lane >> 4) * 16);
        ldsm_x4(qhf[ks], addr);
        ldsm_x4(qlf[ks], addr + 128 * FROW);
    }
    __syncthreads();   // Q staging area will be overwritten by KV buffers

    float o[8][4];
#pragma unroll
    for (int j = 0; j < 8; ++j)
#pragma unroll
        for (int r = 0; r < 4; ++r) o[j][r] = 0.0f;
    float mrun[2] = {-1e30f, -1e30f};
    float lrun[2] = {0.0f, 0.0f};

    f_load_kv(sb, 0, 0, tid, Kp, Vp);
    f_load_kv(sb, 1, 1, tid, Kp, Vp);

    const int NT = NSEQ / 64;   // 32
    for (int kt = 0; kt < NT; ++kt) {
        if (kt < NT - 1)
            asm volatile("cp.async.wait_group 1;\n" ::: "memory");
        else
            asm volatile("cp.async.wait_group 0;\n" ::: "memory");
        __syncthreads();

        if (kt + 2 < NT)
            f_load_kv(sb, (kt + 2) % 3, kt + 2, tid, Kp, Vp);

        const uint32_t kb = sb + (uint32_t)(kt % 3) * FBUF_B;
        const uint32_t vb = kb + KVTILE_B;

        // ---- S = Qh@K^T + Ql@K^T ----
        float sh[8][4];
#pragma unroll
        for (int j = 0; j < 8; ++j)
#pragma unroll
            for (int r = 0; r < 4; ++r) sh[j][r] = 0.0f;

        const int g = lane >> 3;
#pragma unroll
        for (int ks = 0; ks < 4; ++ks) {
            uint32_t kf[4][4];
#pragma unroll
            for (int grp = 0; grp < 4; ++grp) {
                uint32_t addr = kb + (uint32_t)((grp * 16 + (g >> 1) * 8 + (lane & 7)) * FROW
                                                + ks * 32 + (g & 1) * 16);
                ldsm_x4(kf[grp], addr);
            }
#pragma unroll
            for (int j = 0; j < 8; ++j) {
                mma16816_f16(sh[j], qhf[ks], kf[j >> 1][(j & 1) * 2],
                             kf[j >> 1][(j & 1) * 2 + 1]);
                mma16816_f16(sh[j], qlf[ks], kf[j >> 1][(j & 1) * 2],
                             kf[j >> 1][(j & 1) * 2 + 1]);
            }
        }

        // ---- online softmax (log2 domain) ----
        float mx0 = sh[0][0], mx1 = sh[0][2];
#pragma unroll
        for (int j = 0; j < 8; ++j) {
            mx0 = fmaxf(mx0, fmaxf(sh[j][0], sh[j][1]));
            mx1 = fmaxf(mx1, fmaxf(sh[j][2], sh[j][3]));
        }
        mx0 = fmaxf(mx0, __shfl_xor_sync(0xffffffffu, mx0, 1));
        mx0 = fmaxf(mx0, __shfl_xor_sync(0xffffffffu, mx0, 2));
        mx1 = fmaxf(mx1, __shfl_xor_sync(0xffffffffu, mx1, 1));
        mx1 = fmaxf(mx1, __shfl_xor_sync(0xffffffffu, mx1, 2));

        float mn0 = fmaxf(mrun[0], mx0);
        float mn1 = fmaxf(mrun[1], mx1);
        float corr0 = exp2p(mrun[0] - mn0);
        float corr1 = exp2p(mrun[1] - mn1);
        mrun[0] = mn0; mrun[1] = mn1;

        float sum0 = 0.0f, sum1 = 0.0f;
#pragma unroll
        for (int j = 0; j < 8; ++j) {
            sh[j][0] = exp2p(sh[j][0] - mn0);
            sh[j][1] = exp2p(sh[j][1] - mn0);
            sh[j][2] = exp2p(sh[j][2] - mn1);
            sh[j][3] = exp2p(sh[j][3] - mn1);
            sum0 += sh[j][0] + sh[j][1];
            sum1 += sh[j][2] + sh[j][3];
        }
        sum0 += __shfl_xor_sync(0xffffffffu, sum0, 1);
        sum0 += __shfl_xor_sync(0xffffffffu, sum0, 2);
        sum1 += __shfl_xor_sync(0xffffffffu, sum1, 1);
        sum1 += __shfl_xor_sync(0xffffffffu, sum1, 2);
        lrun[0] = lrun[0] * corr0 + sum0;
        lrun[1] = lrun[1] * corr1 + sum1;

#pragma unroll
        for (int j = 0; j < 8; ++j) {
            o[j][0] *= corr0; o[j][1] *= corr0;
            o[j][2] *= corr1; o[j][3] *= corr1;
        }

        // ---- P fragments (register-only conversion) ----
        uint32_t pf[4][4];
#pragma unroll
        for (int t = 0; t < 4; ++t) {
            __half2 p0 = __floats2half2_rn(sh[2*t][0], sh[2*t][1]);
            __half2 p1 = __floats2half2_rn(sh[2*t][2], sh[2*t][3]);
            __half2 p2 = __floats2half2_rn(sh[2*t+1][0], sh[2*t+1][1]);
            __half2 p3 = __floats2half2_rn(sh[2*t+1][2], sh[2*t+1][3]);
            pf[t][0] = *(uint32_t*)&p0;
            pf[t][1] = *(uint32_t*)&p1;
            pf[t][2] = *(uint32_t*)&p2;
            pf[t][3] = *(uint32_t*)&p3;
        }

        // ---- O += P @ V (V via ldmatrix.trans) ----
#pragma unroll
        for (int t = 0; t < 4; ++t) {
            uint32_t vf[4][4];
#pragma unroll
            for (int p = 0; p < 4; ++p) {
                uint32_t addr = vb + (uint32_t)((t * 16 + (g & 1) * 8 + (lane & 7)) * FROW
                                                + (p * 2 + (g >> 1)) * 16);
                ldsm_x4_t(vf[p], addr);
            }
#pragma unroll
            for (int j = 0; j < 8; ++j)
                mma16816_f16(o[j], pf[t], vf[j >> 1][(j & 1) * 2],
                             vf[j >> 1][(j & 1) * 2 + 1]);
        }
    }

    // ---- epilogue: /l, * 1/sqrt(E)=1/32, write ctx [B*N, E] fp32 ----
    const int b = bh >> 4;
    const int h = bh & (HH - 1);
    const int rowA = q0 + wid * 16 + (lane >> 2);
    const int rowB = rowA + 8;
    const float invA = (1.0f / 32.0f) / lrun[0];
    const float invB = (1.0f / 32.0f) / lrun[1];
#pragma unroll
    for (int j = 0; j < 8; ++j) {
        int d = j * 8 + (lane & 3) * 2;
        size_t baseA = ((size_t)(b * NSEQ + rowA)) * EE + h * DD + d;
        size_t baseB = ((size_t)(b * NSEQ + rowB)) * EE + h * DD + d;
        *(float2*)&g_ctx[baseA] = make_float2(o[j][0] * invA, o[j][1] * invA);
        *(float2*)&g_ctx[baseB] = make_float2(o[j][2] * invB, o[j][3] * invB);
    }
}

// ---------------------------------------------------------------------------
extern "C" void kernel_launch(void* const* d_in, const int* in_sizes, int n_in,
                              void* d_out, int out_size)
{
    const float* x  = (const float*)d_in[0];
    const float* Wq = (const float*)d_in[1];
    const float* bq = (const float*)d_in[2];
    const float* Wk = (const float*)d_in[3];
    const float* bk = (const float*)d_in[4];
    const float* Wv = (const float*)d_in[5];
    const float* bv = (const float*)d_in[6];
    const float* Wo = (const float*)d_in[7];
    const float* bo = (const float*)d_in[8];
    float* out = (float*)d_out;

    cudaFuncSetAttribute(mma_gemm, cudaFuncAttributeMaxDynamicSharedMemorySize,
                         GSMEM);
    cudaFuncSetAttribute(flash_mma, cudaFuncAttributeMaxDynamicSharedMemorySize,
                         FSMEM);

    conv_split<<<dim3(1024, 1, 5), 256>>>(x, Wq, Wk, Wv, Wo);

    mma_gemm<<<dim3(EE / 128, MM / 128, 3), 256, GSMEM>>>(
        0, bq, bk, bv, bo, nullptr);

    flash_mma<<<dim3(NSEQ / 128, BB * HH), 256, FSMEM>>>();

    conv_ctx<<<2048, 256>>>();

    mma_gemm<<<dim3(EE / 128, MM / 128, 1), 256, GSMEM>>>(
        1, bq, bk, bv, bo, out);
}

// round 11
// speedup vs baseline: 5.6569x; 1.8542x over previous
#include <cuda_runtime.h>
#include <cuda_fp16.h>
#include <cstdint>

#define BB 2
#define NSEQ 2048
#define EE 1024
#define HH 16
#define DD 64
#define MM (BB*NSEQ)   // 4096
#define LOG2E_F 1.4426950408889634f

// ---------------------------------------------------------------------------
// Scratch (allocation-free __device__ globals) — all fp16 single precision
// ---------------------------------------------------------------------------
__device__ __half g_x16[MM*EE];        // x converted
__device__ __half g_w16[4*EE*EE];      // Wq,Wk,Wv,Wo converted
__device__ __half g_ctx16[MM*EE];      // attention output (token-major)

// attention operands, [B,H,N,D]; Q pre-scaled by log2(e)
__device__ __half g_q16[BB*HH*NSEQ*DD];
__device__ __half g_k16[BB*HH*NSEQ*DD];
__device__ __half g_v16[BB*HH*NSEQ*DD];

// ---------------------------------------------------------------------------
// Helpers (baseline PTX only — sm_80-era features, valid on compute_103 base)
// ---------------------------------------------------------------------------
__device__ __forceinline__ uint32_t smem_to_u32(const void* p) {
    uint32_t a;
    asm("{ .reg .u64 t; cvta.to.shared.u64 t, %1; cvt.u32.u64 %0, t; }"
        : "=r"(a) : "l"(p));
    return a;
}

__device__ __forceinline__ void cp_async16(uint32_t dst, const void* src) {
    asm volatile("cp.async.cg.shared.global [%0], [%1], 16;\n"
                 :: "r"(dst), "l"(src));
}

__device__ __forceinline__ void ldsm_x4(uint32_t* r, uint32_t addr) {
    asm volatile("ldmatrix.sync.aligned.m8n8.x4.shared.b16 {%0,%1,%2,%3}, [%4];"
                 : "=r"(r[0]), "=r"(r[1]), "=r"(r[2]), "=r"(r[3]) : "r"(addr));
}

__device__ __forceinline__ void ldsm_x4_t(uint32_t* r, uint32_t addr) {
    asm volatile("ldmatrix.sync.aligned.m8n8.x4.trans.shared.b16 {%0,%1,%2,%3}, [%4];"
                 : "=r"(r[0]), "=r"(r[1]), "=r"(r[2]), "=r"(r[3]) : "r"(addr));
}

__device__ __forceinline__ void mma16816_f16(float* d, const uint32_t* a,
                                             uint32_t b0, uint32_t b1) {
    asm volatile(
        "mma.sync.aligned.m16n8k16.row.col.f32.f16.f16.f32 "
        "{%0,%1,%2,%3}, {%4,%5,%6,%7}, {%8,%9}, {%0,%1,%2,%3};"
        : "+f"(d[0]), "+f"(d[1]), "+f"(d[2]), "+f"(d[3])
        : "r"(a[0]), "r"(a[1]), "r"(a[2]), "r"(a[3]), "r"(b0), "r"(b1));
}

// exp2 via FFMA pipe (no MUFU): round-trick + degree-5 Taylor, arg clamped
__device__ __forceinline__ float exp2p(float f) {
    f = fmaxf(f, -30.0f);
    float y = f + 12582912.0f;                       // 1.5*2^23
    int n = __float_as_int(y) - 0x4B400000;
    float fr = f - (y - 12582912.0f);                // [-0.5, 0.5]
    float r = 0.0013333558f;
    r = r * fr + 0.0096181291f;
    r = r * fr + 0.0555041087f;
    r = r * fr + 0.2402265070f;
    r = r * fr + 0.6931471806f;
    r = r * fr + 1.0f;
    return r * __int_as_float(0x3F800000 + (n << 23));
}

// ---------------------------------------------------------------------------
// Conversion: fp32 -> fp16. z=0: x -> g_x16; z=1..4: Wq/Wk/Wv/Wo -> g_w16
// ---------------------------------------------------------------------------
__global__ __launch_bounds__(256) void conv_split(const float* __restrict__ x,
                                                  const float* __restrict__ wq,
                                                  const float* __restrict__ wk,
                                                  const float* __restrict__ wv,
                                                  const float* __restrict__ wo)
{
    const int z = blockIdx.z;
    const float* src;
    __half* dst;
    int n;
    if (z == 0) { src = x; dst = g_x16; n = MM * EE; }
    else {
        src = (z == 1) ? wq : (z == 2) ? wk : (z == 3) ? wv : wo;
        dst = g_w16 + (size_t)(z - 1) * EE * EE;
        n = EE * EE;
    }
    int stride = gridDim.x * blockDim.x;
    for (int i = blockIdx.x * blockDim.x + threadIdx.x; i < n; i += stride)
        dst[i] = __float2half_rn(src[i]);
}

// ---------------------------------------------------------------------------
// mma.sync fp16 GEMM (single pass, K=1024): C = A@B^T.
// BM=BN=128, BK=32, 256 threads = 8 warps (2 M x 4 N), warp tile 64x32.
// Smem rows padded to 80 B -> ldmatrix conflict-free. 4-buffer cp.async.
// mode 0: A=g_x16, B=W[blockIdx.z], epilogue fp16 head-split Q(*log2e)/K/V.
// mode 1: A=g_ctx16, B=Wo, write fp32 [M,E] + bias to outp.
// ---------------------------------------------------------------------------
#define BKT 32
#define TOTK (EE / BKT)            // 32
#define TILEB (128 * 40 * 2)       // 10240 B per operand tile (80B rows)
#define STAGE_B (2 * TILEB)        // 20480 B
#define GNBUF 4
#define GSMEM (GNBUF * STAGE_B)    // 81920 B

__device__ __forceinline__ void g_load_stage(uint32_t sb, int s, int tid,
                                             int m0, int n0,
                                             const __half* A, const __half* B)
{
    const int k0 = s * BKT;
    const uint32_t abase = sb + (uint32_t)(s % GNBUF) * STAGE_B;
    const uint32_t bbase = abase + TILEB;
#pragma unroll
    for (int i = 0; i < 2; ++i) {
        int c = tid + i * 256;
        int row = c >> 2;
        int cg  = c & 3;
        uint32_t dst = (uint32_t)(row * 80 + cg * 16);
        cp_async16(abase + dst, A + (size_t)(m0 + row) * EE + k0 + cg * 8);
        cp_async16(bbase + dst, B + (size_t)(n0 + row) * EE + k0 + cg * 8);
    }
    asm volatile("cp.async.commit_group;\n" ::: "memory");
}

__global__ __launch_bounds__(256, 1) void mma_gemm(int mode,
                                                   const float* __restrict__ bq,
                                                   const float* __restrict__ bk,
                                                   const float* __restrict__ bv,
                                                   const float* __restrict__ bo,
                                                   float* __restrict__ outp)
{
    extern __shared__ __align__(16) unsigned char sm_raw[];
    const uint32_t sb = smem_to_u32(sm_raw);

    const int tid = threadIdx.x;
    const int wid = tid >> 5;
    const int lane = tid & 31;
    const int wm = wid >> 2;
    const int wn = wid & 3;
    const int m0 = blockIdx.y * 128;
    const int n0 = blockIdx.x * 128;
    const int widx = (mode == 0) ? (int)blockIdx.z : 3;

    const __half* A = (mode == 0) ? g_x16 : g_ctx16;
    const __half* B = g_w16 + (size_t)widx * EE * EE;

    float acc[4][4][4];
#pragma unroll
    for (int mi = 0; mi < 4; ++mi)
#pragma unroll
        for (int nj = 0; nj < 4; ++nj)
#pragma unroll
            for (int r = 0; r < 4; ++r) acc[mi][nj][r] = 0.0f;

    g_load_stage(sb, 0, tid, m0, n0, A, B);
    g_load_stage(sb, 1, tid, m0, n0, A, B);
    g_load_stage(sb, 2, tid, m0, n0, A, B);

    for (int s = 0; s < TOTK; ++s) {
        if (s < TOTK - 2)
            asm volatile("cp.async.wait_group 2;\n" ::: "memory");
        else if (s == TOTK - 2)
            asm volatile("cp.async.wait_group 1;\n" ::: "memory");
        else
            asm volatile("cp.async.wait_group 0;\n" ::: "memory");
        __syncthreads();

        const uint32_t abuf = sb + (uint32_t)(s % GNBUF) * STAGE_B;
        const uint32_t bbuf = abuf + TILEB;

#pragma unroll
        for (int ks = 0; ks < 2; ++ks) {
            uint32_t af[4][4];
#pragma unroll
            for (int mi = 0; mi < 4; ++mi) {
                int r = wm * 64 + mi * 16 + (lane & 15);
                uint32_t addr = abuf + (uint32_t)(r * 80 + ks * 32 + (lane >> 4) * 16);
                ldsm_x4(af[mi], addr);
            }
            uint32_t bfr[2][4];
#pragma unroll
            for (int np = 0; np < 2; ++np) {
                int g = lane >> 3;
                int r = wn * 32 + np * 16 + (g >> 1) * 8 + (lane & 7);
                uint32_t addr = bbuf + (uint32_t)(r * 80 + ks * 32 + (g & 1) * 16);
                ldsm_x4(bfr[np], addr);
            }
#pragma unroll
            for (int mi = 0; mi < 4; ++mi)
#pragma unroll
                for (int nj = 0; nj < 4; ++nj)
                    mma16816_f16(acc[mi][nj], af[mi],
                                 bfr[nj >> 1][(nj & 1) * 2],
                                 bfr[nj >> 1][(nj & 1) * 2 + 1]);
        }

        if (s + 3 < TOTK)
            g_load_stage(sb, s + 3, tid, m0, n0, A, B);
    }

    const int r_base = m0 + wm * 64 + (lane >> 2);
    const int c_lane = (lane & 3) * 2;

    if (mode == 1) {
#pragma unroll
        for (int mi = 0; mi < 4; ++mi) {
#pragma unroll
            for (int nj = 0; nj < 4; ++nj) {
                int e = n0 + wn * 32 + nj * 8 + c_lane;
                int r = r_base + mi * 16;
                float2 v0 = make_float2(acc[mi][nj][0] + bo[e],
                                        acc[mi][nj][1] + bo[e + 1]);
                *(float2*)&outp[(size_t)r * EE + e] = v0;
                float2 v1 = make_float2(acc[mi][nj][2] + bo[e],
                                        acc[mi][nj][3] + bo[e + 1]);
                *(float2*)&outp[(size_t)(r + 8) * EE + e] = v1;
            }
        }
    } else {
        const float* bias = (widx == 0) ? bq : (widx == 1) ? bk : bv;
        __half* dst = (widx == 0) ? g_q16 : (widx == 1) ? g_k16 : g_v16;
        const float sc = (widx == 0) ? LOG2E_F : 1.0f;
#pragma unroll
        for (int mi = 0; mi < 4; ++mi) {
#pragma unroll
            for (int nj = 0; nj < 4; ++nj) {
                int e = n0 + wn * 32 + nj * 8 + c_lane;
                int h = e >> 6, d = e & (DD - 1);
#pragma unroll
                for (int half = 0; half < 2; ++half) {
                    int m = r_base + mi * 16 + half * 8;
                    int b = m >> 11, n = m & (NSEQ - 1);
                    float v0 = (acc[mi][nj][half * 2 + 0] + bias[e]) * sc;
                    float v1 = (acc[mi][nj][half * 2 + 1] + bias[e + 1]) * sc;
                    size_t idx = (((size_t)(b * HH + h)) * NSEQ + n) * DD + d;
                    *(__half2*)&dst[idx] = __floats2half2_rn(v0, v1);
                }
            }
        }
    }
}

// ---------------------------------------------------------------------------
// HMMA flash attention. Per (b,h): 128 q-rows/CTA, 8 warps x 16 rows.
// S = Q @ K^T (fp16, logits pre-scaled by log2e). Online softmax with exp2
// polynomial (FFMA pipe). O += P @ V in fp16. Epilogue writes fp16 ctx.
// KV: 3-buffer cp.async pipeline, 144B row stride (conflict-free ldmatrix).
// ---------------------------------------------------------------------------
#define FROW 144                  // bytes per smem row (64 fp16 + pad)
#define KVTILE_B (64 * FROW)      // 9216
#define FBUF_B (2 * KVTILE_B)     // K + V per stage: 18432
#define FSMEM (3 * FBUF_B)        // 55296

__device__ __forceinline__ void f_load_kv(uint32_t sb, int buf, int kt, int tid,
                                          const __half* Kp, const __half* Vp)
{
    const uint32_t kb = sb + (uint32_t)buf * FBUF_B;
#pragma unroll
    for (int i = 0; i < 2; ++i) {
        int c = tid + i * 256;       // 0..511
        int row = c >> 3;            // 0..63
        int cg = c & 7;
        uint32_t dst = (uint32_t)(row * FROW + cg * 16);
        cp_async16(kb + dst, Kp + (size_t)(kt * 64 + row) * DD + cg * 8);
        cp_async16(kb + KVTILE_B + dst, Vp + (size_t)(kt * 64 + row) * DD + cg * 8);
    }
    asm volatile("cp.async.commit_group;\n" ::: "memory");
}

__global__ __launch_bounds__(256, 1) void flash_mma()
{
    extern __shared__ __align__(16) unsigned char fsm[];
    const uint32_t sb = smem_to_u32(fsm);

    const int tid = threadIdx.x;
    const int wid = tid >> 5;
    const int lane = tid & 31;
    const int bh = blockIdx.y;
    const int q0 = blockIdx.x * 128;

    const __half* Qp = g_q16 + (size_t)bh * NSEQ * DD + (size_t)q0 * DD;
    const __half* Kp = g_k16 + (size_t)bh * NSEQ * DD;
    const __half* Vp = g_v16 + (size_t)bh * NSEQ * DD;

    // ---- Stage Q and load fragments ----
#pragma unroll
    for (int i = 0; i < 4; ++i) {
        int c = tid + i * 256;       // 0..1023
        int row = c >> 3;            // 0..127
        int cg = c & 7;
        cp_async16(sb + (uint32_t)(row * FROW + cg * 16),
                   Qp + (size_t)row * DD + cg * 8);
    }
    asm volatile("cp.async.commit_group;\n" ::: "memory");
    asm volatile("cp.async.wait_group 0;\n" ::: "memory");
    __syncthreads();

    uint32_t qf[4][4];
#pragma unroll
    for (int ks = 0; ks < 4; ++ks) {
        uint32_t addr = sb + (uint32_t)((wid * 16 + (lane & 15)) * FROW
                                        + ks * 32 + (lane >> 4) * 16);
        ldsm_x4(qf[ks], addr);
    }
    __syncthreads();   // Q staging area will be overwritten by KV buffers

    float o[8][4];
#pragma unroll
    for (int j = 0; j < 8; ++j)
#pragma unroll
        for (int r = 0; r < 4; ++r) o[j][r] = 0.0f;
    float mrun[2] = {-1e30f, -1e30f};
    float lrun[2] = {0.0f, 0.0f};

    f_load_kv(sb, 0, 0, tid, Kp, Vp);
    f_load_kv(sb, 1, 1, tid, Kp, Vp);

    const int NT = NSEQ / 64;   // 32
    for (int kt = 0; kt < NT; ++kt) {
        if (kt < NT - 1)
            asm volatile("cp.async.wait_group 1;\n" ::: "memory");
        else
            asm volatile("cp.async.wait_group 0;\n" ::: "memory");
        __syncthreads();

        if (kt + 2 < NT)
            f_load_kv(sb, (kt + 2) % 3, kt + 2, tid, Kp, Vp);

        const uint32_t kb = sb + (uint32_t)(kt % 3) * FBUF_B;
        const uint32_t vb = kb + KVTILE_B;

        // ---- S = Q @ K^T ----
        float sh[8][4];
#pragma unroll
        for (int j = 0; j < 8; ++j)
#pragma unroll
            for (int r = 0; r < 4; ++r) sh[j][r] = 0.0f;

        const int g = lane >> 3;
#pragma unroll
        for (int ks = 0; ks < 4; ++ks) {
            uint32_t kf[4][4];
#pragma unroll
            for (int grp = 0; grp < 4; ++grp) {
                uint32_t addr = kb + (uint32_t)((grp * 16 + (g >> 1) * 8 + (lane & 7)) * FROW
                                                + ks * 32 + (g & 1) * 16);
                ldsm_x4(kf[grp], addr);
            }
#pragma unroll
            for (int j = 0; j < 8; ++j)
                mma16816_f16(sh[j], qf[ks], kf[j >> 1][(j & 1) * 2],
                             kf[j >> 1][(j & 1) * 2 + 1]);
        }

        // ---- online softmax (log2 domain) ----
        float mx0 = sh[0][0], mx1 = sh[0][2];
#pragma unroll
        for (int j = 0; j < 8; ++j) {
            mx0 = fmaxf(mx0, fmaxf(sh[j][0], sh[j][1]));
            mx1 = fmaxf(mx1, fmaxf(sh[j][2], sh[j][3]));
        }
        mx0 = fmaxf(mx0, __shfl_xor_sync(0xffffffffu, mx0, 1));
        mx0 = fmaxf(mx0, __shfl_xor_sync(0xffffffffu, mx0, 2));
        mx1 = fmaxf(mx1, __shfl_xor_sync(0xffffffffu, mx1, 1));
        mx1 = fmaxf(mx1, __shfl_xor_sync(0xffffffffu, mx1, 2));

        float mn0 = fmaxf(mrun[0], mx0);
        float mn1 = fmaxf(mrun[1], mx1);
        float corr0 = exp2p(mrun[0] - mn0);
        float corr1 = exp2p(mrun[1] - mn1);
        mrun[0] = mn0; mrun[1] = mn1;

        float sum0 = 0.0f, sum1 = 0.0f;
#pragma unroll
        for (int j = 0; j < 8; ++j) {
            sh[j][0] = exp2p(sh[j][0] - mn0);
            sh[j][1] = exp2p(sh[j][1] - mn0);
            sh[j][2] = exp2p(sh[j][2] - mn1);
            sh[j][3] = exp2p(sh[j][3] - mn1);
            sum0 += sh[j][0] + sh[j][1];
            sum1 += sh[j][2] + sh[j][3];
        }
        sum0 += __shfl_xor_sync(0xffffffffu, sum0, 1);
        sum0 += __shfl_xor_sync(0xffffffffu, sum0, 2);
        sum1 += __shfl_xor_sync(0xffffffffu, sum1, 1);
        sum1 += __shfl_xor_sync(0xffffffffu, sum1, 2);
        lrun[0] = lrun[0] * corr0 + sum0;
        lrun[1] = lrun[1] * corr1 + sum1;

#pragma unroll
        for (int j = 0; j < 8; ++j) {
            o[j][0] *= corr0; o[j][1] *= corr0;
            o[j][2] *= corr1; o[j][3] *= corr1;
        }

        // ---- P fragments (register-only conversion) ----
        uint32_t pf[4][4];
#pragma unroll
        for (int t = 0; t < 4; ++t) {
            __half2 p0 = __floats2half2_rn(sh[2*t][0], sh[2*t][1]);
            __half2 p1 = __floats2half2_rn(sh[2*t][2], sh[2*t][3]);
            __half2 p2 = __floats2half2_rn(sh[2*t+1][0], sh[2*t+1][1]);
            __half2 p3 = __floats2half2_rn(sh[2*t+1][2], sh[2*t+1][3]);
            pf[t][0] = *(uint32_t*)&p0;
            pf[t][1] = *(uint32_t*)&p1;
            pf[t][2] = *(uint32_t*)&p2;
            pf[t][3] = *(uint32_t*)&p3;
        }

        // ---- O += P @ V (V via ldmatrix.trans) ----
#pragma unroll
        for (int t = 0; t < 4; ++t) {
            uint32_t vf[4][4];
#pragma unroll
            for (int p = 0; p < 4; ++p) {
                uint32_t addr = vb + (uint32_t)((t * 16 + (g & 1) * 8 + (lane & 7)) * FROW
                                                + (p * 2 + (g >> 1)) * 16);
                ldsm_x4_t(vf[p], addr);
            }
#pragma unroll
            for (int j = 0; j < 8; ++j)
                mma16816_f16(o[j], pf[t], vf[j >> 1][(j & 1) * 2],
                             vf[j >> 1][(j & 1) * 2 + 1]);
        }
    }

    // ---- epilogue: /l, * 1/32, write fp16 ctx [B*N, E] ----
    const int b = bh >> 4;
    const int h = bh & (HH - 1);
    const int rowA = q0 + wid * 16 + (lane >> 2);
    const int rowB = rowA + 8;
    const float invA = (1.0f / 32.0f) / lrun[0];
    const float invB = (1.0f / 32.0f) / lrun[1];
#pragma unroll
    for (int j = 0; j < 8; ++j) {
        int d = j * 8 + (lane & 3) * 2;
        size_t baseA = ((size_t)(b * NSEQ + rowA)) * EE + h * DD + d;
        size_t baseB = ((size_t)(b * NSEQ + rowB)) * EE + h * DD + d;
        *(__half2*)&g_ctx16[baseA] = __floats2half2_rn(o[j][0] * invA, o[j][1] * invA);
        *(__half2*)&g_ctx16[baseB] = __floats2half2_rn(o[j][2] * invB, o[j][3] * invB);
    }
}

// ---------------------------------------------------------------------------
extern "C" void kernel_launch(void* const* d_in, const int* in_sizes, int n_in,
                              void* d_out, int out_size)
{
    const float* x  = (const float*)d_in[0];
    const float* Wq = (const float*)d_in[1];
    const float* bq = (const float*)d_in[2];
    const float* Wk = (const float*)d_in[3];
    const float* bk = (const float*)d_in[4];
    const float* Wv = (const float*)d_in[5];
    const float* bv = (const float*)d_in[6];
    const float* Wo = (const float*)d_in[7];
    const float* bo = (const float*)d_in[8];
    float* out = (float*)d_out;

    cudaFuncSetAttribute(mma_gemm, cudaFuncAttributeMaxDynamicSharedMemorySize,
                         GSMEM);
    cudaFuncSetAttribute(flash_mma, cudaFuncAttributeMaxDynamicSharedMemorySize,
                         FSMEM);

    conv_split<<<dim3(512, 1, 5), 256>>>(x, Wq, Wk, Wv, Wo);

    mma_gemm<<<dim3(EE / 128, MM / 128, 3), 256, GSMEM>>>(
        0, bq, bk, bv, bo, nullptr);

    flash_mma<<<dim3(NSEQ / 128, BB * HH), 256, FSMEM>>>();

    mma_gemm<<<dim3(EE / 128, MM / 128, 1), 256, GSMEM>>>(
        1, bq, bk, bv, bo, out);
}

// round 12
// speedup vs baseline: 6.4726x; 1.1442x over previous
#include <cuda_runtime.h>
#include <cuda_fp16.h>
#include <cstdint>

#define BB 2
#define NSEQ 2048
#define EE 1024
#define HH 16
#define DD 64
#define MM (BB*NSEQ)   // 4096
#define LOG2E_F 1.4426950408889634f

// ---------------------------------------------------------------------------
// Scratch (allocation-free __device__ globals) — all fp16 single precision
// ---------------------------------------------------------------------------
__device__ __half g_x16[MM*EE];        // x converted
__device__ __half g_w16[4*EE*EE];      // Wq,Wk,Wv,Wo converted
__device__ __half g_ctx16[MM*EE];      // attention output (token-major)

// attention operands, [B,H,N,D]; Q pre-scaled by log2(e)
__device__ __half g_q16[BB*HH*NSEQ*DD];
__device__ __half g_k16[BB*HH*NSEQ*DD];
__device__ __half g_v16[BB*HH*NSEQ*DD];

// ---------------------------------------------------------------------------
// Helpers (baseline PTX only — sm_80-era features, valid on compute_103 base)
// ---------------------------------------------------------------------------
__device__ __forceinline__ uint32_t smem_to_u32(const void* p) {
    uint32_t a;
    asm("{ .reg .u64 t; cvta.to.shared.u64 t, %1; cvt.u32.u64 %0, t; }"
        : "=r"(a) : "l"(p));
    return a;
}

__device__ __forceinline__ void cp_async16(uint32_t dst, const void* src) {
    asm volatile("cp.async.cg.shared.global [%0], [%1], 16;\n"
                 :: "r"(dst), "l"(src));
}

__device__ __forceinline__ void ldsm_x4(uint32_t* r, uint32_t addr) {
    asm volatile("ldmatrix.sync.aligned.m8n8.x4.shared.b16 {%0,%1,%2,%3}, [%4];"
                 : "=r"(r[0]), "=r"(r[1]), "=r"(r[2]), "=r"(r[3]) : "r"(addr));
}

__device__ __forceinline__ void ldsm_x4_t(uint32_t* r, uint32_t addr) {
    asm volatile("ldmatrix.sync.aligned.m8n8.x4.trans.shared.b16 {%0,%1,%2,%3}, [%4];"
                 : "=r"(r[0]), "=r"(r[1]), "=r"(r[2]), "=r"(r[3]) : "r"(addr));
}

__device__ __forceinline__ void mma16816_f16(float* d, const uint32_t* a,
                                             uint32_t b0, uint32_t b1) {
    asm volatile(
        "mma.sync.aligned.m16n8k16.row.col.f32.f16.f16.f32 "
        "{%0,%1,%2,%3}, {%4,%5,%6,%7}, {%8,%9}, {%0,%1,%2,%3};"
        : "+f"(d[0]), "+f"(d[1]), "+f"(d[2]), "+f"(d[3])
        : "r"(a[0]), "r"(a[1]), "r"(a[2]), "r"(a[3]), "r"(b0), "r"(b1));
}

// exp2 via FFMA pipe (no MUFU): round-trick + degree-5 Taylor, arg clamped
__device__ __forceinline__ float exp2p(float f) {
    f = fmaxf(f, -30.0f);
    float y = f + 12582912.0f;                       // 1.5*2^23
    int n = __float_as_int(y) - 0x4B400000;
    float fr = f - (y - 12582912.0f);                // [-0.5, 0.5]
    float r = 0.0013333558f;
    r = r * fr + 0.0096181291f;
    r = r * fr + 0.0555041087f;
    r = r * fr + 0.2402265070f;
    r = r * fr + 0.6931471806f;
    r = r * fr + 1.0f;
    return r * __int_as_float(0x3F800000 + (n << 23));
}

// ---------------------------------------------------------------------------
// Conversion: fp32 -> fp16. z=0: x -> g_x16; z=1..4: Wq/Wk/Wv/Wo -> g_w16
// ---------------------------------------------------------------------------
__global__ __launch_bounds__(256) void conv_split(const float* __restrict__ x,
                                                  const float* __restrict__ wq,
                                                  const float* __restrict__ wk,
                                                  const float* __restrict__ wv,
                                                  const float* __restrict__ wo)
{
    const int z = blockIdx.z;
    const float* src;
    __half* dst;
    int n;
    if (z == 0) { src = x; dst = g_x16; n = MM * EE; }
    else {
        src = (z == 1) ? wq : (z == 2) ? wk : (z == 3) ? wv : wo;
        dst = g_w16 + (size_t)(z - 1) * EE * EE;
        n = EE * EE;
    }
    int stride = gridDim.x * blockDim.x;
    for (int i = blockIdx.x * blockDim.x + threadIdx.x; i < n; i += stride)
        dst[i] = __float2half_rn(src[i]);
}

// ---------------------------------------------------------------------------
// mma.sync fp16 GEMM (single pass, K=1024): C = A@B^T.
// BM=BN=128, BK=32, 256 threads = 8 warps (2 M x 4 N), warp tile 64x32.
// Smem rows padded to 80 B -> ldmatrix conflict-free. 4-buffer cp.async.
// __launch_bounds__(256, 2): cap regs at 128 so 2 CTAs co-reside per SM
// (R11 ncu: regs=154 -> 1 CTA/SM, occ 12.3%, tensor 35% = latency-bound).
// mode 0: A=g_x16, B=W[blockIdx.z], epilogue fp16 head-split Q(*log2e)/K/V.
// mode 1: A=g_ctx16, B=Wo, write fp32 [M,E] + bias to outp.
// ---------------------------------------------------------------------------
#define BKT 32
#define TOTK (EE / BKT)            // 32
#define TILEB (128 * 40 * 2)       // 10240 B per operand tile (80B rows)
#define STAGE_B (2 * TILEB)        // 20480 B
#define GNBUF 4
#define GSMEM (GNBUF * STAGE_B)    // 81920 B

__device__ __forceinline__ void g_load_stage(uint32_t sb, int s, int tid,
                                             int m0, int n0,
                                             const __half* A, const __half* B)
{
    const int k0 = s * BKT;
    const uint32_t abase = sb + (uint32_t)(s % GNBUF) * STAGE_B;
    const uint32_t bbase = abase + TILEB;
#pragma unroll
    for (int i = 0; i < 2; ++i) {
        int c = tid + i * 256;
        int row = c >> 2;
        int cg  = c & 3;
        uint32_t dst = (uint32_t)(row * 80 + cg * 16);
        cp_async16(abase + dst, A + (size_t)(m0 + row) * EE + k0 + cg * 8);
        cp_async16(bbase + dst, B + (size_t)(n0 + row) * EE + k0 + cg * 8);
    }
    asm volatile("cp.async.commit_group;\n" ::: "memory");
}

__global__ __launch_bounds__(256, 2) void mma_gemm(int mode,
                                                   const float* __restrict__ bq,
                                                   const float* __restrict__ bk,
                                                   const float* __restrict__ bv,
                                                   const float* __restrict__ bo,
                                                   float* __restrict__ outp)
{
    extern __shared__ __align__(16) unsigned char sm_raw[];
    const uint32_t sb = smem_to_u32(sm_raw);

    const int tid = threadIdx.x;
    const int wid = tid >> 5;
    const int lane = tid & 31;
    const int wm = wid >> 2;
    const int wn = wid & 3;
    const int m0 = blockIdx.y * 128;
    const int n0 = blockIdx.x * 128;
    const int widx = (mode == 0) ? (int)blockIdx.z : 3;

    const __half* A = (mode == 0) ? g_x16 : g_ctx16;
    const __half* B = g_w16 + (size_t)widx * EE * EE;

    float acc[4][4][4];
#pragma unroll
    for (int mi = 0; mi < 4; ++mi)
#pragma unroll
        for (int nj = 0; nj < 4; ++nj)
#pragma unroll
            for (int r = 0; r < 4; ++r) acc[mi][nj][r] = 0.0f;

    g_load_stage(sb, 0, tid, m0, n0, A, B);
    g_load_stage(sb, 1, tid, m0, n0, A, B);
    g_load_stage(sb, 2, tid, m0, n0, A, B);

    for (int s = 0; s < TOTK; ++s) {
        if (s < TOTK - 2)
            asm volatile("cp.async.wait_group 2;\n" ::: "memory");
        else if (s == TOTK - 2)
            asm volatile("cp.async.wait_group 1;\n" ::: "memory");
        else
            asm volatile("cp.async.wait_group 0;\n" ::: "memory");
        __syncthreads();

        const uint32_t abuf = sb + (uint32_t)(s % GNBUF) * STAGE_B;
        const uint32_t bbuf = abuf + TILEB;

#pragma unroll
        for (int ks = 0; ks < 2; ++ks) {
            uint32_t af[4][4];
#pragma unroll
            for (int mi = 0; mi < 4; ++mi) {
                int r = wm * 64 + mi * 16 + (lane & 15);
                uint32_t addr = abuf + (uint32_t)(r * 80 + ks * 32 + (lane >> 4) * 16);
                ldsm_x4(af[mi], addr);
            }
            uint32_t bfr[2][4];
#pragma unroll
            for (int np = 0; np < 2; ++np) {
                int g = lane >> 3;
                int r = wn * 32 + np * 16 + (g >> 1) * 8 + (lane & 7);
                uint32_t addr = bbuf + (uint32_t)(r * 80 + ks * 32 + (g & 1) * 16);
                ldsm_x4(bfr[np], addr);
            }
#pragma unroll
            for (int mi = 0; mi < 4; ++mi)
#pragma unroll
                for (int nj = 0; nj < 4; ++nj)
                    mma16816_f16(acc[mi][nj], af[mi],
                                 bfr[nj >> 1][(nj & 1) * 2],
                                 bfr[nj >> 1][(nj & 1) * 2 + 1]);
        }

        if (s + 3 < TOTK)
            g_load_stage(sb, s + 3, tid, m0, n0, A, B);
    }

    const int r_base = m0 + wm * 64 + (lane >> 2);
    const int c_lane = (lane & 3) * 2;

    if (mode == 1) {
#pragma unroll
        for (int mi = 0; mi < 4; ++mi) {
#pragma unroll
            for (int nj = 0; nj < 4; ++nj) {
                int e = n0 + wn * 32 + nj * 8 + c_lane;
                int r = r_base + mi * 16;
                float2 v0 = make_float2(acc[mi][nj][0] + bo[e],
                                        acc[mi][nj][1] + bo[e + 1]);
                *(float2*)&outp[(size_t)r * EE + e] = v0;
                float2 v1 = make_float2(acc[mi][nj][2] + bo[e],
                                        acc[mi][nj][3] + bo[e + 1]);
                *(float2*)&outp[(size_t)(r + 8) * EE + e] = v1;
            }
        }
    } else {
        const float* bias = (widx == 0) ? bq : (widx == 1) ? bk : bv;
        __half* dst = (widx == 0) ? g_q16 : (widx == 1) ? g_k16 : g_v16;
        const float sc = (widx == 0) ? LOG2E_F : 1.0f;
#pragma unroll
        for (int mi = 0; mi < 4; ++mi) {
#pragma unroll
            for (int nj = 0; nj < 4; ++nj) {
                int e = n0 + wn * 32 + nj * 8 + c_lane;
                int h = e >> 6, d = e & (DD - 1);
#pragma unroll
                for (int half = 0; half < 2; ++half) {
                    int m = r_base + mi * 16 + half * 8;
                    int b = m >> 11, n = m & (NSEQ - 1);
                    float v0 = (acc[mi][nj][half * 2 + 0] + bias[e]) * sc;
                    float v1 = (acc[mi][nj][half * 2 + 1] + bias[e + 1]) * sc;
                    size_t idx = (((size_t)(b * HH + h)) * NSEQ + n) * DD + d;
                    *(__half2*)&dst[idx] = __floats2half2_rn(v0, v1);
                }
            }
        }
    }
}

// ---------------------------------------------------------------------------
// HMMA flash attention. Per (b,h): 128 q-rows/CTA, 8 warps x 16 rows.
// S = Q @ K^T (fp16, logits pre-scaled by log2e). Online softmax with exp2
// polynomial (FFMA pipe). O += P @ V in fp16. Epilogue writes fp16 ctx.
// KV: 3-buffer cp.async pipeline, 144B row stride (conflict-free ldmatrix).
// __launch_bounds__(256, 2): 2 CTAs/SM (smem 2x55296 fits; hides LDSM/sync).
// ---------------------------------------------------------------------------
#define FROW 144                  // bytes per smem row (64 fp16 + pad)
#define KVTILE_B (64 * FROW)      // 9216
#define FBUF_B (2 * KVTILE_B)     // K + V per stage: 18432
#define FSMEM (3 * FBUF_B)        // 55296

__device__ __forceinline__ void f_load_kv(uint32_t sb, int buf, int kt, int tid,
                                          const __half* Kp, const __half* Vp)
{
    const uint32_t kb = sb + (uint32_t)buf * FBUF_B;
#pragma unroll
    for (int i = 0; i < 2; ++i) {
        int c = tid + i * 256;       // 0..511
        int row = c >> 3;            // 0..63
        int cg = c & 7;
        uint32_t dst = (uint32_t)(row * FROW + cg * 16);
        cp_async16(kb + dst, Kp + (size_t)(kt * 64 + row) * DD + cg * 8);
        cp_async16(kb + KVTILE_B + dst, Vp + (size_t)(kt * 64 + row) * DD + cg * 8);
    }
    asm volatile("cp.async.commit_group;\n" ::: "memory");
}

__global__ __launch_bounds__(256, 2) void flash_mma()
{
    extern __shared__ __align__(16) unsigned char fsm[];
    const uint32_t sb = smem_to_u32(fsm);

    const int tid = threadIdx.x;
    const int wid = tid >> 5;
    const int lane = tid & 31;
    const int bh = blockIdx.y;
    const int q0 = blockIdx.x * 128;

    const __half* Qp = g_q16 + (size_t)bh * NSEQ * DD + (size_t)q0 * DD;
    const __half* Kp = g_k16 + (size_t)bh * NSEQ * DD;
    const __half* Vp = g_v16 + (size_t)bh * NSEQ * DD;

    // ---- Stage Q and load fragments ----
#pragma unroll
    for (int i = 0; i < 4; ++i) {
        int c = tid + i * 256;       // 0..1023
        int row = c >> 3;            // 0..127
        int cg = c & 7;
        cp_async16(sb + (uint32_t)(row * FROW + cg * 16),
                   Qp + (size_t)row * DD + cg * 8);
    }
    asm volatile("cp.async.commit_group;\n" ::: "memory");
    asm volatile("cp.async.wait_group 0;\n" ::: "memory");
    __syncthreads();

    uint32_t qf[4][4];
#pragma unroll
    for (int ks = 0; ks < 4; ++ks) {
        uint32_t addr = sb + (uint32_t)((wid * 16 + (lane & 15)) * FROW
                                        + ks * 32 + (lane >> 4) * 16);
        ldsm_x4(qf[ks], addr);
    }
    __syncthreads();   // Q staging area will be overwritten by KV buffers

    float o[8][4];
#pragma unroll
    for (int j = 0; j < 8; ++j)
#pragma unroll
        for (int r = 0; r < 4; ++r) o[j][r] = 0.0f;
    float mrun[2] = {-1e30f, -1e30f};
    float lrun[2] = {0.0f, 0.0f};

    f_load_kv(sb, 0, 0, tid, Kp, Vp);
    f_load_kv(sb, 1, 1, tid, Kp, Vp);

    const int NT = NSEQ / 64;   // 32
    for (int kt = 0; kt < NT; ++kt) {
        if (kt < NT - 1)
            asm volatile("cp.async.wait_group 1;\n" ::: "memory");
        else
            asm volatile("cp.async.wait_group 0;\n" ::: "memory");
        __syncthreads();

        if (kt + 2 < NT)
            f_load_kv(sb, (kt + 2) % 3, kt + 2, tid, Kp, Vp);

        const uint32_t kb = sb + (uint32_t)(kt % 3) * FBUF_B;
        const uint32_t vb = kb + KVTILE_B;

        // ---- S = Q @ K^T ----
        float sh[8][4];
#pragma unroll
        for (int j = 0; j < 8; ++j)
#pragma unroll
            for (int r = 0; r < 4; ++r) sh[j][r] = 0.0f;

        const int g = lane >> 3;
#pragma unroll
        for (int ks = 0; ks < 4; ++ks) {
            uint32_t kf[4][4];
#pragma unroll
            for (int grp = 0; grp < 4; ++grp) {
                uint32_t addr = kb + (uint32_t)((grp * 16 + (g >> 1) * 8 + (lane & 7)) * FROW
                                                + ks * 32 + (g & 1) * 16);
                ldsm_x4(kf[grp], addr);
            }
#pragma unroll
            for (int j = 0; j < 8; ++j)
                mma16816_f16(sh[j], qf[ks], kf[j >> 1][(j & 1) * 2],
                             kf[j >> 1][(j & 1) * 2 + 1]);
        }

        // ---- online softmax (log2 domain) ----
        float mx0 = sh[0][0], mx1 = sh[0][2];
#pragma unroll
        for (int j = 0; j < 8; ++j) {
            mx0 = fmaxf(mx0, fmaxf(sh[j][0], sh[j][1]));
            mx1 = fmaxf(mx1, fmaxf(sh[j][2], sh[j][3]));
        }
        mx0 = fmaxf(mx0, __shfl_xor_sync(0xffffffffu, mx0, 1));
        mx0 = fmaxf(mx0, __shfl_xor_sync(0xffffffffu, mx0, 2));
        mx1 = fmaxf(mx1, __shfl_xor_sync(0xffffffffu, mx1, 1));
        mx1 = fmaxf(mx1, __shfl_xor_sync(0xffffffffu, mx1, 2));

        float mn0 = fmaxf(mrun[0], mx0);
        float mn1 = fmaxf(mrun[1], mx1);
        float corr0 = exp2p(mrun[0] - mn0);
        float corr1 = exp2p(mrun[1] - mn1);
        mrun[0] = mn0; mrun[1] = mn1;

        float sum0 = 0.0f, sum1 = 0.0f;
#pragma unroll
        for (int j = 0; j < 8; ++j) {
            sh[j][0] = exp2p(sh[j][0] - mn0);
            sh[j][1] = exp2p(sh[j][1] - mn0);
            sh[j][2] = exp2p(sh[j][2] - mn1);
            sh[j][3] = exp2p(sh[j][3] - mn1);
            sum0 += sh[j][0] + sh[j][1];
            sum1 += sh[j][2] + sh[j][3];
        }
        sum0 += __shfl_xor_sync(0xffffffffu, sum0, 1);
        sum0 += __shfl_xor_sync(0xffffffffu, sum0, 2);
        sum1 += __shfl_xor_sync(0xffffffffu, sum1, 1);
        sum1 += __shfl_xor_sync(0xffffffffu, sum1, 2);
        lrun[0] = lrun[0] * corr0 + sum0;
        lrun[1] = lrun[1] * corr1 + sum1;

#pragma unroll
        for (int j = 0; j < 8; ++j) {
            o[j][0] *= corr0; o[j][1] *= corr0;
            o[j][2] *= corr1; o[j][3] *= corr1;
        }

        // ---- P fragments (register-only conversion) ----
        uint32_t pf[4][4];
#pragma unroll
        for (int t = 0; t < 4; ++t) {
            __half2 p0 = __floats2half2_rn(sh[2*t][0], sh[2*t][1]);
            __half2 p1 = __floats2half2_rn(sh[2*t][2], sh[2*t][3]);
            __half2 p2 = __floats2half2_rn(sh[2*t+1][0], sh[2*t+1][1]);
            __half2 p3 = __floats2half2_rn(sh[2*t+1][2], sh[2*t+1][3]);
            pf[t][0] = *(uint32_t*)&p0;
            pf[t][1] = *(uint32_t*)&p1;
            pf[t][2] = *(uint32_t*)&p2;
            pf[t][3] = *(uint32_t*)&p3;
        }

        // ---- O += P @ V (V via ldmatrix.trans) ----
#pragma unroll
        for (int t = 0; t < 4; ++t) {
            uint32_t vf[4][4];
#pragma unroll
            for (int p = 0; p < 4; ++p) {
                uint32_t addr = vb + (uint32_t)((t * 16 + (g & 1) * 8 + (lane & 7)) * FROW
                                                + (p * 2 + (g >> 1)) * 16);
                ldsm_x4_t(vf[p], addr);
            }
#pragma unroll
            for (int j = 0; j < 8; ++j)
                mma16816_f16(o[j], pf[t], vf[j >> 1][(j & 1) * 2],
                             vf[j >> 1][(j & 1) * 2 + 1]);
        }
    }

    // ---- epilogue: /l, * 1/32, write fp16 ctx [B*N, E] ----
    const int b = bh >> 4;
    const int h = bh & (HH - 1);
    const int rowA = q0 + wid * 16 + (lane >> 2);
    const int rowB = rowA + 8;
    const float invA = (1.0f / 32.0f) / lrun[0];
    const float invB = (1.0f / 32.0f) / lrun[1];
#pragma unroll
    for (int j = 0; j < 8; ++j) {
        int d = j * 8 + (lane & 3) * 2;
        size_t baseA = ((size_t)(b * NSEQ + rowA)) * EE + h * DD + d;
        size_t baseB = ((size_t)(b * NSEQ + rowB)) * EE + h * DD + d;
        *(__half2*)&g_ctx16[baseA] = __floats2half2_rn(o[j][0] * invA, o[j][1] * invA);
        *(__half2*)&g_ctx16[baseB] = __floats2half2_rn(o[j][2] * invB, o[j][3] * invB);
    }
}

// ---------------------------------------------------------------------------
extern "C" void kernel_launch(void* const* d_in, const int* in_sizes, int n_in,
                              void* d_out, int out_size)
{
    const float* x  = (const float*)d_in[0];
    const float* Wq = (const float*)d_in[1];
    const float* bq = (const float*)d_in[2];
    const float* Wk = (const float*)d_in[3];
    const float* bk = (const float*)d_in[4];
    const float* Wv = (const float*)d_in[5];
    const float* bv = (const float*)d_in[6];
    const float* Wo = (const float*)d_in[7];
    const float* bo = (const float*)d_in[8];
    float* out = (float*)d_out;

    cudaFuncSetAttribute(mma_gemm, cudaFuncAttributeMaxDynamicSharedMemorySize,
                         GSMEM);
    cudaFuncSetAttribute(flash_mma, cudaFuncAttributeMaxDynamicSharedMemorySize,
                         FSMEM);

    conv_split<<<dim3(512, 1, 5), 256>>>(x, Wq, Wk, Wv, Wo);

    mma_gemm<<<dim3(EE / 128, MM / 128, 3), 256, GSMEM>>>(
        0, bq, bk, bv, bo, nullptr);

    flash_mma<<<dim3(NSEQ / 128, BB * HH), 256, FSMEM>>>();

    mma_gemm<<<dim3(EE / 128, MM / 128, 1), 256, GSMEM>>>(
        1, bq, bk, bv, bo, out);
}